// round 6
// baseline (speedup 1.0000x reference)
#include <cuda_runtime.h>
#include <cstdint>

#define BB 4
#define SS 2048
#define DD 1024
#define HH 16
#define HD 64

// Scratch (allocation-free)
__device__ float g_q[(size_t)BB * HH * SS * HD];   // q [B,H,S,hd] (tf32-rounded)
__device__ float g_a[(size_t)BB * SS * DD];        // attention out (tf32-rounded)
__device__ float g_xr[(size_t)BB * SS * DD];       // x rounded to tf32
__device__ float g_war[(size_t)3 * DD * DD];       // w_attn rounded to tf32
__device__ float g_wt[(size_t)DD * DD];            // w_proj^T rounded to tf32
__device__ float g_kr[(size_t)BB * HH * SS * HD];  // k rounded (attention input)
__device__ float g_vr[(size_t)BB * HH * SS * HD];  // v rounded (attention input)

// ---------------------------------------------------------------------------
__device__ __forceinline__ uint32_t smem_u32(const void* p) {
    uint32_t a;
    asm("{ .reg .u64 t; cvta.to.shared.u64 t, %1; cvt.u32.u64 %0, t; }"
        : "=r"(a) : "l"(p));
    return a;
}
__device__ __forceinline__ uint32_t f2tf(float f) {
    uint32_t u;
    asm("cvt.rna.tf32.f32 %0, %1;" : "=r"(u) : "f"(f));
    return u;
}
__device__ __forceinline__ void cp_async16(uint32_t dst, const void* src) {
    asm volatile("cp.async.cg.shared.global [%0], [%1], 16;" :: "r"(dst), "l"(src));
}
#define CP_COMMIT() asm volatile("cp.async.commit_group;" ::: "memory")
#define CP_WAIT(n)  asm volatile("cp.async.wait_group %0;" :: "n"(n) : "memory")

__device__ __forceinline__ void mma_tf32(float* c, const uint32_t* a, const uint32_t* b) {
    asm volatile(
        "mma.sync.aligned.m16n8k8.row.col.f32.tf32.tf32.f32 "
        "{%0,%1,%2,%3}, {%4,%5,%6,%7}, {%8,%9}, {%0,%1,%2,%3};"
        : "+f"(c[0]), "+f"(c[1]), "+f"(c[2]), "+f"(c[3])
        : "r"(a[0]), "r"(a[1]), "r"(a[2]), "r"(a[3]), "r"(b[0]), "r"(b[1]));
}

// ---------------------------------------------------------------------------
// Elementwise round-to-tf32
// ---------------------------------------------------------------------------
__global__ __launch_bounds__(256) void round_kernel(
    const float4* __restrict__ in, float4* __restrict__ out, int n4)
{
    int i = blockIdx.x * blockDim.x + threadIdx.x;
    int stride = gridDim.x * blockDim.x;
    for (; i < n4; i += stride) {
        float4 v = in[i];
        float4 o;
        o.x = __uint_as_float(f2tf(v.x));
        o.y = __uint_as_float(f2tf(v.y));
        o.z = __uint_as_float(f2tf(v.z));
        o.w = __uint_as_float(f2tf(v.w));
        out[i] = o;
    }
}

__global__ __launch_bounds__(256) void transpose_round_kernel(
    const float* __restrict__ in, float* __restrict__ out)
{
    __shared__ float t[32][33];
    const int tx = threadIdx.x, ty = threadIdx.y;
    const int k0 = blockIdx.y * 32;
    const int n0 = blockIdx.x * 32;
#pragma unroll
    for (int i = ty; i < 32; i += 8)
        t[i][tx] = in[(size_t)(k0 + i) * DD + n0 + tx];
    __syncthreads();
#pragma unroll
    for (int i = ty; i < 32; i += 8)
        out[(size_t)(n0 + i) * DD + k0 + tx] = __uint_as_float(f2tf(t[tx][i]));
}

// ---------------------------------------------------------------------------
// tf32 mma.sync GEMM: CTA tile 128x256, warp tile 64x64, BK=32, 3 stages.
// MODE 0: C -> out0. MODE 1: q->g_q (rounded), k->out1 + g_kr, v->out2 + g_vr.
// ---------------------------------------------------------------------------
#define KDIM 1024
#define NCHUNK (KDIM / 32)
#define ROWSTRIDE 36
#define A_STG 4608                       // 128*36 floats
#define B_STG 9216                       // 256*36 floats
#define STG_F (A_STG + B_STG)            // 13824 floats per stage
#define GEMM_SMEM (3 * STG_F * 4)        // 165888 bytes

template <int MODE>
__global__ __launch_bounds__(256, 1) void mma_gemm(
    const float* __restrict__ A, const float* __restrict__ Bm,
    const float* __restrict__ bias,
    float* __restrict__ out0, float* __restrict__ out1, float* __restrict__ out2)
{
    extern __shared__ float sm[];
    const uint32_t sbase = smem_u32(sm);
    const int tid = threadIdx.x;
    const int wid = tid >> 5;
    const int lane = tid & 31;
    const int g = lane >> 2;
    const int tig = lane & 3;
    const int m0 = blockIdx.y * 128;
    const int n0 = blockIdx.x * 256;
    const int wm = (wid & 1) * 64;       // warp M offset
    const int wn = (wid >> 1) * 64;      // warp N offset

    float c[4][8][4];
#pragma unroll
    for (int i = 0; i < 4; i++)
#pragma unroll
        for (int j = 0; j < 8; j++)
#pragma unroll
            for (int k = 0; k < 4; k++) c[i][j][k] = 0.f;

    const int lrow = tid >> 3;           // 0..31
    const int lcol = (tid & 7) * 4;      // 0..28
    const float* Abase = A + (size_t)m0 * KDIM;
    const float* Bbase = Bm + (size_t)n0 * KDIM;

#define ISSUE(chunk) do {                                                           \
    const int _k0 = (chunk) * 32;                                                   \
    const uint32_t _as = sbase + (uint32_t)((chunk) % 3) * STG_F * 4;               \
    const uint32_t _bs = _as + A_STG * 4;                                           \
    _Pragma("unroll")                                                               \
    for (int _i = 0; _i < 4; _i++) {                                                \
        const int _r = lrow + _i * 32;                                              \
        cp_async16(_as + (uint32_t)(_r * ROWSTRIDE + lcol) * 4,                     \
                   Abase + (size_t)_r * KDIM + _k0 + lcol);                         \
    }                                                                               \
    _Pragma("unroll")                                                               \
    for (int _i = 0; _i < 8; _i++) {                                                \
        const int _r = lrow + _i * 32;                                              \
        cp_async16(_bs + (uint32_t)(_r * ROWSTRIDE + lcol) * 4,                     \
                   Bbase + (size_t)_r * KDIM + _k0 + lcol);                         \
    }                                                                               \
    CP_COMMIT();                                                                    \
} while (0)

    ISSUE(0);
    ISSUE(1);

    for (int ch = 0; ch < NCHUNK; ch++) {
        __syncthreads();                 // all warps done with stage (ch+2)%3 reads
        if (ch + 2 < NCHUNK) {
            ISSUE(ch + 2);
            CP_WAIT(2);
        } else if (ch + 1 < NCHUNK) {
            CP_WAIT(1);
        } else {
            CP_WAIT(0);
        }
        __syncthreads();                 // stage ch%3 visible to all

        const float* As_ = sm + (ch % 3) * STG_F;
        const float* Bs_ = As_ + A_STG;
#pragma unroll
        for (int ks = 0; ks < 4; ks++) {
            const int kc = ks * 8 + tig;
            uint32_t af[4][4], bf[8][2];
#pragma unroll
            for (int mt = 0; mt < 4; mt++) {
                const int r = wm + mt * 16 + g;
                af[mt][0] = __float_as_uint(As_[r * ROWSTRIDE + kc]);
                af[mt][1] = __float_as_uint(As_[(r + 8) * ROWSTRIDE + kc]);
                af[mt][2] = __float_as_uint(As_[r * ROWSTRIDE + kc + 4]);
                af[mt][3] = __float_as_uint(As_[(r + 8) * ROWSTRIDE + kc + 4]);
            }
#pragma unroll
            for (int nt = 0; nt < 8; nt++) {
                const int rn = wn + nt * 8 + g;
                bf[nt][0] = __float_as_uint(Bs_[rn * ROWSTRIDE + kc]);
                bf[nt][1] = __float_as_uint(Bs_[rn * ROWSTRIDE + kc + 4]);
            }
#pragma unroll
            for (int mt = 0; mt < 4; mt++)
#pragma unroll
                for (int nt = 0; nt < 8; nt++)
                    mma_tf32(c[mt][nt], af[mt], bf[nt]);
        }
    }

#pragma unroll
    for (int mt = 0; mt < 4; mt++) {
        const int row0 = m0 + wm + mt * 16 + g;
        const int row1 = row0 + 8;
#pragma unroll
        for (int nt = 0; nt < 8; nt++) {
            const int n = n0 + wn + nt * 8 + 2 * tig;
            const float2 bv = *(const float2*)(bias + n);
            float2 v0, v1;
            v0.x = c[mt][nt][0] + bv.x; v0.y = c[mt][nt][1] + bv.y;
            v1.x = c[mt][nt][2] + bv.x; v1.y = c[mt][nt][3] + bv.y;
            if (MODE == 0) {
                *(float2*)(out0 + (size_t)row0 * DD + n) = v0;
                *(float2*)(out0 + (size_t)row1 * DD + n) = v1;
            } else {
                const int part = n >> 10;
                const int hc = n & (DD - 1);
                const int h = hc >> 6;
                const int d = hc & 63;
                const int b0_ = row0 >> 11, s0_ = row0 & (SS - 1);
                const int b1_ = row1 >> 11, s1_ = row1 & (SS - 1);
                const size_t d0 = (((size_t)(b0_ * HH + h)) * SS + s0_) * HD + d;
                const size_t d1 = (((size_t)(b1_ * HH + h)) * SS + s1_) * HD + d;
                float2 r0v, r1v;
                r0v.x = __uint_as_float(f2tf(v0.x)); r0v.y = __uint_as_float(f2tf(v0.y));
                r1v.x = __uint_as_float(f2tf(v1.x)); r1v.y = __uint_as_float(f2tf(v1.y));
                if (part == 0) {
                    *(float2*)(g_q + d0) = r0v;
                    *(float2*)(g_q + d1) = r1v;
                } else if (part == 1) {
                    *(float2*)(out1 + d0) = v0;       // exact -> present
                    *(float2*)(out1 + d1) = v1;
                    *(float2*)(g_kr + d0) = r0v;      // rounded -> attention
                    *(float2*)(g_kr + d1) = r1v;
                } else {
                    *(float2*)(out2 + d0) = v0;
                    *(float2*)(out2 + d1) = v1;
                    *(float2*)(g_vr + d0) = r0v;
                    *(float2*)(g_vr + d1) = r1v;
                }
            }
        }
    }
}

// ---------------------------------------------------------------------------
// Tensor-core causal flash attention (unchanged from round 5).
// CTA: 256 threads (8 warps), 128 queries. Key tiles of 64, cp.async x2 stages.
// ---------------------------------------------------------------------------
#define KSTR 76
#define PSTR 68
#define KVSTG 19456u                         // 64*76*4
#define AKS_OFF(s) ((uint32_t)(s) * KVSTG)
#define AVS_OFF(s) (2u * KVSTG + (uint32_t)(s) * KVSTG)
#define APS_OFF (4u * KVSTG)                 // 77824
#define ATT_SMEM (APS_OFF + 128u * PSTR * 4u)  // 112640 bytes

__global__ __launch_bounds__(256, 1) void attn_tc(
    const float* __restrict__ kr, const float* __restrict__ vr)
{
    extern __shared__ char smc[];
    float* smf = (float*)smc;
    const uint32_t sb = smem_u32(smc);
    const int tid = threadIdx.x;
    const int w = tid >> 5, lane = tid & 31;
    const int g = lane >> 2, tig = lane & 3;
    const int bh = blockIdx.x;
    const int qblk = blockIdx.y;
    const int q0 = qblk * 128;
    const int tmax = 2 * qblk + 1;
    const float* kbase = kr + (size_t)bh * SS * HD;
    const float* vbase = vr + (size_t)bh * SS * HD;

#define AISSUE(t) do {                                                            \
    const int _st = (t) & 1;                                                      \
    const int _k0 = (t) * 64;                                                     \
    _Pragma("unroll")                                                             \
    for (int _i = 0; _i < 4; _i++) {                                              \
        const int _f = tid + 256 * _i;                                            \
        const int _r = _f >> 4;                                                   \
        const int _c = (_f & 15) << 2;                                            \
        cp_async16(sb + AKS_OFF(_st) + (uint32_t)(_r * KSTR + _c) * 4,            \
                   kbase + (size_t)(_k0 + _r) * HD + _c);                         \
        cp_async16(sb + AVS_OFF(_st) + (uint32_t)(_r * KSTR + _c) * 4,            \
                   vbase + (size_t)(_k0 + _r) * HD + _c);                         \
    }                                                                             \
    CP_COMMIT();                                                                  \
} while (0)

    {
        const float* qbase = g_q + ((size_t)bh * SS + q0) * HD;
#pragma unroll
        for (int i = 0; i < 8; i++) {
            const int f = tid + 256 * i;
            const int r = f >> 4;
            const int c = (f & 15) << 2;
            cp_async16(sb + APS_OFF + (uint32_t)(r * PSTR + c) * 4,
                       qbase + (size_t)r * HD + c);
        }
        CP_COMMIT();
    }
    AISSUE(0);
    CP_WAIT(1);
    __syncthreads();

    const int r0 = w * 16 + g;

    uint32_t qa[8][4];
    {
        const float* Q = smf + APS_OFF / 4;
#pragma unroll
        for (int kc = 0; kc < 8; kc++) {
            qa[kc][0] = __float_as_uint(Q[r0 * PSTR + kc * 8 + tig] * 0.125f);
            qa[kc][1] = __float_as_uint(Q[(r0 + 8) * PSTR + kc * 8 + tig] * 0.125f);
            qa[kc][2] = __float_as_uint(Q[r0 * PSTR + kc * 8 + tig + 4] * 0.125f);
            qa[kc][3] = __float_as_uint(Q[(r0 + 8) * PSTR + kc * 8 + tig + 4] * 0.125f);
        }
    }
    __syncthreads();

    float o[8][4];
#pragma unroll
    for (int i = 0; i < 8; i++)
#pragma unroll
        for (int j = 0; j < 4; j++) o[i][j] = 0.f;
    float m0 = -1e30f, m1 = -1e30f, l0 = 0.f, l1 = 0.f;

    for (int t = 0; t <= tmax; t++) {
        const int st = t & 1;
        if (t < tmax) AISSUE(t + 1);
        if (t < tmax) { CP_WAIT(1); } else { CP_WAIT(0); }
        __syncthreads();

        float s[8][4];
#pragma unroll
        for (int i = 0; i < 8; i++)
#pragma unroll
            for (int j = 0; j < 4; j++) s[i][j] = 0.f;

        const float* Ks = smf + AKS_OFF(st) / 4;
#pragma unroll
        for (int kc = 0; kc < 8; kc++) {
            uint32_t kb[8][2];
#pragma unroll
            for (int nt = 0; nt < 8; nt++) {
                kb[nt][0] = __float_as_uint(Ks[(8 * nt + g) * KSTR + 8 * kc + tig]);
                kb[nt][1] = __float_as_uint(Ks[(8 * nt + g) * KSTR + 8 * kc + tig + 4]);
            }
#pragma unroll
            for (int nt = 0; nt < 8; nt++)
                mma_tf32(s[nt], qa[kc], kb[nt]);
        }

        if (t >= 2 * qblk) {
            const int qg0 = q0 + r0;
            const int qg1 = qg0 + 8;
            const int kb0 = t * 64;
#pragma unroll
            for (int nt = 0; nt < 8; nt++) {
                const int col = kb0 + 8 * nt + 2 * tig;
                if (col > qg0)     s[nt][0] = -1e30f;
                if (col + 1 > qg0) s[nt][1] = -1e30f;
                if (col > qg1)     s[nt][2] = -1e30f;
                if (col + 1 > qg1) s[nt][3] = -1e30f;
            }
        }

        float mx0 = -1e30f, mx1 = -1e30f;
#pragma unroll
        for (int nt = 0; nt < 8; nt++) {
            mx0 = fmaxf(mx0, fmaxf(s[nt][0], s[nt][1]));
            mx1 = fmaxf(mx1, fmaxf(s[nt][2], s[nt][3]));
        }
        mx0 = fmaxf(mx0, __shfl_xor_sync(0xffffffffu, mx0, 1));
        mx0 = fmaxf(mx0, __shfl_xor_sync(0xffffffffu, mx0, 2));
        mx1 = fmaxf(mx1, __shfl_xor_sync(0xffffffffu, mx1, 1));
        mx1 = fmaxf(mx1, __shfl_xor_sync(0xffffffffu, mx1, 2));

        const float mn0 = fmaxf(m0, mx0);
        const float mn1 = fmaxf(m1, mx1);
        const float a0 = __expf(m0 - mn0);
        const float a1 = __expf(m1 - mn1);
        m0 = mn0; m1 = mn1;
        l0 *= a0; l1 *= a1;
#pragma unroll
        for (int nt = 0; nt < 8; nt++) {
            o[nt][0] *= a0; o[nt][1] *= a0;
            o[nt][2] *= a1; o[nt][3] *= a1;
        }

        float* Ps = smf + APS_OFF / 4;
        float rs0 = 0.f, rs1 = 0.f;
#pragma unroll
        for (int nt = 0; nt < 8; nt++) {
            const float p0 = __expf(s[nt][0] - mn0);
            const float p1 = __expf(s[nt][1] - mn0);
            const float p2 = __expf(s[nt][2] - mn1);
            const float p3 = __expf(s[nt][3] - mn1);
            rs0 += p0 + p1;
            rs1 += p2 + p3;
            float2 w0, w1;
            w0.x = __uint_as_float(f2tf(p0)); w0.y = __uint_as_float(f2tf(p1));
            w1.x = __uint_as_float(f2tf(p2)); w1.y = __uint_as_float(f2tf(p3));
            *(float2*)(Ps + r0 * PSTR + 8 * nt + 2 * tig) = w0;
            *(float2*)(Ps + (r0 + 8) * PSTR + 8 * nt + 2 * tig) = w1;
        }
        rs0 += __shfl_xor_sync(0xffffffffu, rs0, 1);
        rs0 += __shfl_xor_sync(0xffffffffu, rs0, 2);
        rs1 += __shfl_xor_sync(0xffffffffu, rs1, 1);
        rs1 += __shfl_xor_sync(0xffffffffu, rs1, 2);
        l0 += rs0; l1 += rs1;

        __syncwarp();

        const float* Vs = smf + AVS_OFF(st) / 4;
#pragma unroll
        for (int kc = 0; kc < 8; kc++) {
            uint32_t af[4];
            af[0] = __float_as_uint(Ps[r0 * PSTR + 8 * kc + tig]);
            af[1] = __float_as_uint(Ps[(r0 + 8) * PSTR + 8 * kc + tig]);
            af[2] = __float_as_uint(Ps[r0 * PSTR + 8 * kc + tig + 4]);
            af[3] = __float_as_uint(Ps[(r0 + 8) * PSTR + 8 * kc + tig + 4]);
            uint32_t vb[8][2];
#pragma unroll
            for (int nt = 0; nt < 8; nt++) {
                vb[nt][0] = __float_as_uint(Vs[(8 * kc + tig) * KSTR + 8 * nt + g]);
                vb[nt][1] = __float_as_uint(Vs[(8 * kc + tig + 4) * KSTR + 8 * nt + g]);
            }
#pragma unroll
            for (int nt = 0; nt < 8; nt++)
                mma_tf32(o[nt], af, vb[nt]);
        }
        __syncthreads();
    }

    const float inv0 = 1.0f / l0;
    const float inv1 = 1.0f / l1;
    const int b = bh >> 4, h = bh & 15;
    const size_t base0 = ((size_t)b * SS + q0 + r0) * DD + h * 64;
    const size_t base1 = ((size_t)b * SS + q0 + r0 + 8) * DD + h * 64;
#pragma unroll
    for (int nt = 0; nt < 8; nt++) {
        const int col = 8 * nt + 2 * tig;
        float2 w0, w1;
        w0.x = __uint_as_float(f2tf(o[nt][0] * inv0));
        w0.y = __uint_as_float(f2tf(o[nt][1] * inv0));
        w1.x = __uint_as_float(f2tf(o[nt][2] * inv1));
        w1.y = __uint_as_float(f2tf(o[nt][3] * inv1));
        *(float2*)(g_a + base0 + col) = w0;
        *(float2*)(g_a + base1 + col) = w1;
    }
}

// ---------------------------------------------------------------------------
extern "C" void kernel_launch(void* const* d_in, const int* in_sizes, int n_in,
                              void* d_out, int out_size)
{
    const float* x      = (const float*)d_in[0];
    const float* w_attn = (const float*)d_in[1];
    const float* b_attn = (const float*)d_in[2];
    const float* w_proj = (const float*)d_in[3];
    const float* b_proj = (const float*)d_in[4];

    float* out  = (float*)d_out;
    float* kout = out + (size_t)BB * SS * DD;
    float* vout = kout + (size_t)BB * HH * SS * HD;

    float *xr, *war, *wt, *ga, *kr, *vr;
    cudaGetSymbolAddress((void**)&xr, g_xr);
    cudaGetSymbolAddress((void**)&war, g_war);
    cudaGetSymbolAddress((void**)&wt, g_wt);
    cudaGetSymbolAddress((void**)&ga, g_a);
    cudaGetSymbolAddress((void**)&kr, g_kr);
    cudaGetSymbolAddress((void**)&vr, g_vr);

    cudaFuncSetAttribute(mma_gemm<0>, cudaFuncAttributeMaxDynamicSharedMemorySize, GEMM_SMEM);
    cudaFuncSetAttribute(mma_gemm<1>, cudaFuncAttributeMaxDynamicSharedMemorySize, GEMM_SMEM);
    cudaFuncSetAttribute(attn_tc, cudaFuncAttributeMaxDynamicSharedMemorySize, ATT_SMEM);

    // Pre-round GEMM inputs to tf32
    round_kernel<<<1024, 256>>>((const float4*)x, (float4*)xr, BB * SS * DD / 4);
    round_kernel<<<1024, 256>>>((const float4*)w_attn, (float4*)war, 3 * DD * DD / 4);
    transpose_round_kernel<<<dim3(32, 32), dim3(32, 8)>>>(w_proj, wt);

    // QKV GEMM: q(rounded)->g_q, k/v exact->present + rounded->g_kr/g_vr
    mma_gemm<1><<<dim3(3 * DD / 256, BB * SS / 128), 256, GEMM_SMEM>>>(
        xr, war, b_attn, nullptr, kout, vout);

    // Tensor-core flash attention -> g_a (tf32-rounded)
    attn_tc<<<dim3(BB * HH, SS / 128), 256, ATT_SMEM>>>(kr, vr);

    // Proj GEMM -> out
    mma_gemm<0><<<dim3(DD / 256, BB * SS / 128), 256, GEMM_SMEM>>>(
        ga, wt, b_proj, out, nullptr, nullptr);
}

// round 7
// speedup vs baseline: 1.0713x; 1.0713x over previous
#include <cuda_runtime.h>
#include <cstdint>

#define BB 4
#define SS 2048
#define DD 1024
#define HH 16
#define HD 64

// Scratch (allocation-free)
__device__ float g_q[(size_t)BB * HH * SS * HD];   // q [B,H,S,hd] (tf32-rounded)
__device__ float g_a[(size_t)BB * SS * DD];        // attention out (tf32-rounded)
__device__ float g_xr[(size_t)BB * SS * DD];       // x rounded to tf32
__device__ float g_war[(size_t)3 * DD * DD];       // w_attn rounded to tf32
__device__ float g_wt[(size_t)DD * DD];            // w_proj^T rounded to tf32
__device__ float g_kr[(size_t)BB * HH * SS * HD];  // k rounded (attention input)
__device__ float g_vr[(size_t)BB * HH * SS * HD];  // v rounded (attention input)

// ---------------------------------------------------------------------------
__device__ __forceinline__ uint32_t smem_u32(const void* p) {
    uint32_t a;
    asm("{ .reg .u64 t; cvta.to.shared.u64 t, %1; cvt.u32.u64 %0, t; }"
        : "=r"(a) : "l"(p));
    return a;
}
__device__ __forceinline__ uint32_t f2tf(float f) {
    uint32_t u;
    asm("cvt.rna.tf32.f32 %0, %1;" : "=r"(u) : "f"(f));
    return u;
}
__device__ __forceinline__ void cp_async16(uint32_t dst, const void* src) {
    asm volatile("cp.async.cg.shared.global [%0], [%1], 16;" :: "r"(dst), "l"(src));
}
#define CP_COMMIT() asm volatile("cp.async.commit_group;" ::: "memory")
#define CP_WAIT(n)  asm volatile("cp.async.wait_group %0;" :: "n"(n) : "memory")

__device__ __forceinline__ void mma_tf32(float* c, const uint32_t* a, const uint32_t* b) {
    asm volatile(
        "mma.sync.aligned.m16n8k8.row.col.f32.tf32.tf32.f32 "
        "{%0,%1,%2,%3}, {%4,%5,%6,%7}, {%8,%9}, {%0,%1,%2,%3};"
        : "+f"(c[0]), "+f"(c[1]), "+f"(c[2]), "+f"(c[3])
        : "r"(a[0]), "r"(a[1]), "r"(a[2]), "r"(a[3]), "r"(b[0]), "r"(b[1]));
}

// ---------------------------------------------------------------------------
// Elementwise round-to-tf32
// ---------------------------------------------------------------------------
__global__ __launch_bounds__(256) void round_kernel(
    const float4* __restrict__ in, float4* __restrict__ out, int n4)
{
    int i = blockIdx.x * blockDim.x + threadIdx.x;
    int stride = gridDim.x * blockDim.x;
    for (; i < n4; i += stride) {
        float4 v = in[i];
        float4 o;
        o.x = __uint_as_float(f2tf(v.x));
        o.y = __uint_as_float(f2tf(v.y));
        o.z = __uint_as_float(f2tf(v.z));
        o.w = __uint_as_float(f2tf(v.w));
        out[i] = o;
    }
}

__global__ __launch_bounds__(256) void transpose_round_kernel(
    const float* __restrict__ in, float* __restrict__ out)
{
    __shared__ float t[32][33];
    const int tx = threadIdx.x, ty = threadIdx.y;
    const int k0 = blockIdx.y * 32;
    const int n0 = blockIdx.x * 32;
#pragma unroll
    for (int i = ty; i < 32; i += 8)
        t[i][tx] = in[(size_t)(k0 + i) * DD + n0 + tx];
    __syncthreads();
#pragma unroll
    for (int i = ty; i < 32; i += 8)
        out[(size_t)(n0 + i) * DD + k0 + tx] = __uint_as_float(f2tf(t[tx][i]));
}

// ---------------------------------------------------------------------------
// tf32 mma.sync GEMM: 128x128 CTA tile, 32x64 warp tile, BK=32,
// 3-stage cp.async pipeline, 2 CTAs/SM.
// MODE 0: C -> out0. MODE 1: q->g_q (rounded), k->out1 + g_kr, v->out2 + g_vr.
// ---------------------------------------------------------------------------
#define KDIM 1024
#define NCHUNK (KDIM / 32)
#define STG_F 9216                 // (128+128)*36 floats per stage
#define ROWSTRIDE 36
#define GEMM_SMEM (3 * STG_F * 4)  // 110592 bytes

template <int MODE>
__global__ __launch_bounds__(256, 2) void mma_gemm(
    const float* __restrict__ A, const float* __restrict__ Bm,
    const float* __restrict__ bias,
    float* __restrict__ out0, float* __restrict__ out1, float* __restrict__ out2)
{
    extern __shared__ float sm[];
    const uint32_t sbase = smem_u32(sm);
    const int tid = threadIdx.x;
    const int wid = tid >> 5;
    const int lane = tid & 31;
    const int g = lane >> 2;
    const int tig = lane & 3;
    const int m0 = blockIdx.y * 128;
    const int n0 = blockIdx.x * 128;
    const int wm = (wid & 3) * 32;
    const int wn = (wid >> 2) * 64;

    float c[2][8][4];
#pragma unroll
    for (int i = 0; i < 2; i++)
#pragma unroll
        for (int j = 0; j < 8; j++)
#pragma unroll
            for (int k = 0; k < 4; k++) c[i][j][k] = 0.f;

    const int lrow = tid >> 3;
    const int lcol = (tid & 7) * 4;
    const float* Abase = A + (size_t)m0 * KDIM;
    const float* Bbase = Bm + (size_t)n0 * KDIM;

#define ISSUE(chunk) do {                                                           \
    const int _k0 = (chunk) * 32;                                                   \
    const uint32_t _as = sbase + (uint32_t)((chunk) % 3) * STG_F * 4;               \
    const uint32_t _bs = _as + 4608 * 4;                                            \
    _Pragma("unroll")                                                               \
    for (int _i = 0; _i < 4; _i++) {                                                \
        const int _r = lrow + _i * 32;                                              \
        cp_async16(_as + (uint32_t)(_r * ROWSTRIDE + lcol) * 4,                     \
                   Abase + (size_t)_r * KDIM + _k0 + lcol);                         \
        cp_async16(_bs + (uint32_t)(_r * ROWSTRIDE + lcol) * 4,                     \
                   Bbase + (size_t)_r * KDIM + _k0 + lcol);                         \
    }                                                                               \
    CP_COMMIT();                                                                    \
} while (0)

    ISSUE(0);
    ISSUE(1);

    for (int ch = 0; ch < NCHUNK; ch++) {
        __syncthreads();                 // readers of stage (ch+2)%3 (chunk ch-1) done
        if (ch + 2 < NCHUNK) {
            ISSUE(ch + 2);
            CP_WAIT(2);
        } else if (ch + 1 < NCHUNK) {
            CP_WAIT(1);
        } else {
            CP_WAIT(0);
        }
        __syncthreads();                 // stage ch%3 visible to all

        const float* As_ = sm + (ch % 3) * STG_F;
        const float* Bs_ = As_ + 4608;
#pragma unroll
        for (int ks = 0; ks < 4; ks++) {
            const int kc = ks * 8 + tig;
            uint32_t af[2][4], bf[8][2];
#pragma unroll
            for (int mt = 0; mt < 2; mt++) {
                const int r = wm + mt * 16 + g;
                af[mt][0] = __float_as_uint(As_[r * ROWSTRIDE + kc]);
                af[mt][1] = __float_as_uint(As_[(r + 8) * ROWSTRIDE + kc]);
                af[mt][2] = __float_as_uint(As_[r * ROWSTRIDE + kc + 4]);
                af[mt][3] = __float_as_uint(As_[(r + 8) * ROWSTRIDE + kc + 4]);
            }
#pragma unroll
            for (int nt = 0; nt < 8; nt++) {
                const int rn = wn + nt * 8 + g;
                bf[nt][0] = __float_as_uint(Bs_[rn * ROWSTRIDE + kc]);
                bf[nt][1] = __float_as_uint(Bs_[rn * ROWSTRIDE + kc + 4]);
            }
#pragma unroll
            for (int mt = 0; mt < 2; mt++)
#pragma unroll
                for (int nt = 0; nt < 8; nt++)
                    mma_tf32(c[mt][nt], af[mt], bf[nt]);
        }
    }

#pragma unroll
    for (int mt = 0; mt < 2; mt++) {
        const int row0 = m0 + wm + mt * 16 + g;
        const int row1 = row0 + 8;
#pragma unroll
        for (int nt = 0; nt < 8; nt++) {
            const int n = n0 + wn + nt * 8 + 2 * tig;
            const float2 bv = *(const float2*)(bias + n);
            float2 v0, v1;
            v0.x = c[mt][nt][0] + bv.x; v0.y = c[mt][nt][1] + bv.y;
            v1.x = c[mt][nt][2] + bv.x; v1.y = c[mt][nt][3] + bv.y;
            if (MODE == 0) {
                *(float2*)(out0 + (size_t)row0 * DD + n) = v0;
                *(float2*)(out0 + (size_t)row1 * DD + n) = v1;
            } else {
                const int part = n >> 10;
                const int hc = n & (DD - 1);
                const int h = hc >> 6;
                const int d = hc & 63;
                const int b0_ = row0 >> 11, s0_ = row0 & (SS - 1);
                const int b1_ = row1 >> 11, s1_ = row1 & (SS - 1);
                const size_t d0 = (((size_t)(b0_ * HH + h)) * SS + s0_) * HD + d;
                const size_t d1 = (((size_t)(b1_ * HH + h)) * SS + s1_) * HD + d;
                float2 r0v, r1v;
                r0v.x = __uint_as_float(f2tf(v0.x)); r0v.y = __uint_as_float(f2tf(v0.y));
                r1v.x = __uint_as_float(f2tf(v1.x)); r1v.y = __uint_as_float(f2tf(v1.y));
                if (part == 0) {
                    *(float2*)(g_q + d0) = r0v;
                    *(float2*)(g_q + d1) = r1v;
                } else if (part == 1) {
                    *(float2*)(out1 + d0) = v0;       // exact -> present
                    *(float2*)(out1 + d1) = v1;
                    *(float2*)(g_kr + d0) = r0v;      // rounded -> attention
                    *(float2*)(g_kr + d1) = r1v;
                } else {
                    *(float2*)(out2 + d0) = v0;
                    *(float2*)(out2 + d1) = v1;
                    *(float2*)(g_vr + d0) = r0v;
                    *(float2*)(g_vr + d1) = r1v;
                }
            }
        }
    }
}

// ---------------------------------------------------------------------------
// Tensor-core causal flash attention. Heaviest q-blocks scheduled first.
// CTA: 256 threads (8 warps), 128 queries. Key tiles of 64, cp.async x2 stages.
// ---------------------------------------------------------------------------
#define KSTR 76
#define PSTR 68
#define KVSTG 19456u                         // 64*76*4
#define AKS_OFF(s) ((uint32_t)(s) * KVSTG)
#define AVS_OFF(s) (2u * KVSTG + (uint32_t)(s) * KVSTG)
#define APS_OFF (4u * KVSTG)                 // 77824
#define ATT_SMEM (APS_OFF + 128u * PSTR * 4u)  // 112640 bytes

__global__ __launch_bounds__(256, 1) void attn_tc(
    const float* __restrict__ kr, const float* __restrict__ vr)
{
    extern __shared__ char smc[];
    float* smf = (float*)smc;
    const uint32_t sb = smem_u32(smc);
    const int tid = threadIdx.x;
    const int w = tid >> 5, lane = tid & 31;
    const int g = lane >> 2, tig = lane & 3;
    const int bh = blockIdx.x;
    const int qblk = (gridDim.y - 1) - blockIdx.y;   // big blocks first
    const int q0 = qblk * 128;
    const int tmax = 2 * qblk + 1;
    const float* kbase = kr + (size_t)bh * SS * HD;
    const float* vbase = vr + (size_t)bh * SS * HD;

#define AISSUE(t) do {                                                            \
    const int _st = (t) & 1;                                                      \
    const int _k0 = (t) * 64;                                                     \
    _Pragma("unroll")                                                             \
    for (int _i = 0; _i < 4; _i++) {                                              \
        const int _f = tid + 256 * _i;                                            \
        const int _r = _f >> 4;                                                   \
        const int _c = (_f & 15) << 2;                                            \
        cp_async16(sb + AKS_OFF(_st) + (uint32_t)(_r * KSTR + _c) * 4,            \
                   kbase + (size_t)(_k0 + _r) * HD + _c);                         \
        cp_async16(sb + AVS_OFF(_st) + (uint32_t)(_r * KSTR + _c) * 4,            \
                   vbase + (size_t)(_k0 + _r) * HD + _c);                         \
    }                                                                             \
    CP_COMMIT();                                                                  \
} while (0)

    {
        const float* qbase = g_q + ((size_t)bh * SS + q0) * HD;
#pragma unroll
        for (int i = 0; i < 8; i++) {
            const int f = tid + 256 * i;
            const int r = f >> 4;
            const int c = (f & 15) << 2;
            cp_async16(sb + APS_OFF + (uint32_t)(r * PSTR + c) * 4,
                       qbase + (size_t)r * HD + c);
        }
        CP_COMMIT();
    }
    AISSUE(0);
    CP_WAIT(1);
    __syncthreads();

    const int r0 = w * 16 + g;

    uint32_t qa[8][4];
    {
        const float* Q = smf + APS_OFF / 4;
#pragma unroll
        for (int kc = 0; kc < 8; kc++) {
            qa[kc][0] = __float_as_uint(Q[r0 * PSTR + kc * 8 + tig] * 0.125f);
            qa[kc][1] = __float_as_uint(Q[(r0 + 8) * PSTR + kc * 8 + tig] * 0.125f);
            qa[kc][2] = __float_as_uint(Q[r0 * PSTR + kc * 8 + tig + 4] * 0.125f);
            qa[kc][3] = __float_as_uint(Q[(r0 + 8) * PSTR + kc * 8 + tig + 4] * 0.125f);
        }
    }
    __syncthreads();

    float o[8][4];
#pragma unroll
    for (int i = 0; i < 8; i++)
#pragma unroll
        for (int j = 0; j < 4; j++) o[i][j] = 0.f;
    float m0 = -1e30f, m1 = -1e30f, l0 = 0.f, l1 = 0.f;

    for (int t = 0; t <= tmax; t++) {
        const int st = t & 1;
        if (t < tmax) AISSUE(t + 1);
        if (t < tmax) { CP_WAIT(1); } else { CP_WAIT(0); }
        __syncthreads();

        float s[8][4];
#pragma unroll
        for (int i = 0; i < 8; i++)
#pragma unroll
            for (int j = 0; j < 4; j++) s[i][j] = 0.f;

        const float* Ks = smf + AKS_OFF(st) / 4;
#pragma unroll
        for (int kc = 0; kc < 8; kc++) {
            uint32_t kb[8][2];
#pragma unroll
            for (int nt = 0; nt < 8; nt++) {
                kb[nt][0] = __float_as_uint(Ks[(8 * nt + g) * KSTR + 8 * kc + tig]);
                kb[nt][1] = __float_as_uint(Ks[(8 * nt + g) * KSTR + 8 * kc + tig + 4]);
            }
#pragma unroll
            for (int nt = 0; nt < 8; nt++)
                mma_tf32(s[nt], qa[kc], kb[nt]);
        }

        if (t >= 2 * qblk) {
            const int qg0 = q0 + r0;
            const int qg1 = qg0 + 8;
            const int kb0 = t * 64;
#pragma unroll
            for (int nt = 0; nt < 8; nt++) {
                const int col = kb0 + 8 * nt + 2 * tig;
                if (col > qg0)     s[nt][0] = -1e30f;
                if (col + 1 > qg0) s[nt][1] = -1e30f;
                if (col > qg1)     s[nt][2] = -1e30f;
                if (col + 1 > qg1) s[nt][3] = -1e30f;
            }
        }

        float mx0 = -1e30f, mx1 = -1e30f;
#pragma unroll
        for (int nt = 0; nt < 8; nt++) {
            mx0 = fmaxf(mx0, fmaxf(s[nt][0], s[nt][1]));
            mx1 = fmaxf(mx1, fmaxf(s[nt][2], s[nt][3]));
        }
        mx0 = fmaxf(mx0, __shfl_xor_sync(0xffffffffu, mx0, 1));
        mx0 = fmaxf(mx0, __shfl_xor_sync(0xffffffffu, mx0, 2));
        mx1 = fmaxf(mx1, __shfl_xor_sync(0xffffffffu, mx1, 1));
        mx1 = fmaxf(mx1, __shfl_xor_sync(0xffffffffu, mx1, 2));

        const float mn0 = fmaxf(m0, mx0);
        const float mn1 = fmaxf(m1, mx1);
        const float a0 = __expf(m0 - mn0);
        const float a1 = __expf(m1 - mn1);
        m0 = mn0; m1 = mn1;
        l0 *= a0; l1 *= a1;
#pragma unroll
        for (int nt = 0; nt < 8; nt++) {
            o[nt][0] *= a0; o[nt][1] *= a0;
            o[nt][2] *= a1; o[nt][3] *= a1;
        }

        float* Ps = smf + APS_OFF / 4;
        float rs0 = 0.f, rs1 = 0.f;
#pragma unroll
        for (int nt = 0; nt < 8; nt++) {
            const float p0 = __expf(s[nt][0] - mn0);
            const float p1 = __expf(s[nt][1] - mn0);
            const float p2 = __expf(s[nt][2] - mn1);
            const float p3 = __expf(s[nt][3] - mn1);
            rs0 += p0 + p1;
            rs1 += p2 + p3;
            float2 w0, w1;
            w0.x = __uint_as_float(f2tf(p0)); w0.y = __uint_as_float(f2tf(p1));
            w1.x = __uint_as_float(f2tf(p2)); w1.y = __uint_as_float(f2tf(p3));
            *(float2*)(Ps + r0 * PSTR + 8 * nt + 2 * tig) = w0;
            *(float2*)(Ps + (r0 + 8) * PSTR + 8 * nt + 2 * tig) = w1;
        }
        rs0 += __shfl_xor_sync(0xffffffffu, rs0, 1);
        rs0 += __shfl_xor_sync(0xffffffffu, rs0, 2);
        rs1 += __shfl_xor_sync(0xffffffffu, rs1, 1);
        rs1 += __shfl_xor_sync(0xffffffffu, rs1, 2);
        l0 += rs0; l1 += rs1;

        __syncwarp();

        const float* Vs = smf + AVS_OFF(st) / 4;
#pragma unroll
        for (int kc = 0; kc < 8; kc++) {
            uint32_t af[4];
            af[0] = __float_as_uint(Ps[r0 * PSTR + 8 * kc + tig]);
            af[1] = __float_as_uint(Ps[(r0 + 8) * PSTR + 8 * kc + tig]);
            af[2] = __float_as_uint(Ps[r0 * PSTR + 8 * kc + tig + 4]);
            af[3] = __float_as_uint(Ps[(r0 + 8) * PSTR + 8 * kc + tig + 4]);
            uint32_t vb[8][2];
#pragma unroll
            for (int nt = 0; nt < 8; nt++) {
                vb[nt][0] = __float_as_uint(Vs[(8 * kc + tig) * KSTR + 8 * nt + g]);
                vb[nt][1] = __float_as_uint(Vs[(8 * kc + tig + 4) * KSTR + 8 * nt + g]);
            }
#pragma unroll
            for (int nt = 0; nt < 8; nt++)
                mma_tf32(o[nt], af, vb[nt]);
        }
        __syncthreads();
    }

    const float inv0 = 1.0f / l0;
    const float inv1 = 1.0f / l1;
    const int b = bh >> 4, h = bh & 15;
    const size_t base0 = ((size_t)b * SS + q0 + r0) * DD + h * 64;
    const size_t base1 = ((size_t)b * SS + q0 + r0 + 8) * DD + h * 64;
#pragma unroll
    for (int nt = 0; nt < 8; nt++) {
        const int col = 8 * nt + 2 * tig;
        float2 w0, w1;
        w0.x = __uint_as_float(f2tf(o[nt][0] * inv0));
        w0.y = __uint_as_float(f2tf(o[nt][1] * inv0));
        w1.x = __uint_as_float(f2tf(o[nt][2] * inv1));
        w1.y = __uint_as_float(f2tf(o[nt][3] * inv1));
        *(float2*)(g_a + base0 + col) = w0;
        *(float2*)(g_a + base1 + col) = w1;
    }
}

// ---------------------------------------------------------------------------
extern "C" void kernel_launch(void* const* d_in, const int* in_sizes, int n_in,
                              void* d_out, int out_size)
{
    const float* x      = (const float*)d_in[0];
    const float* w_attn = (const float*)d_in[1];
    const float* b_attn = (const float*)d_in[2];
    const float* w_proj = (const float*)d_in[3];
    const float* b_proj = (const float*)d_in[4];

    float* out  = (float*)d_out;
    float* kout = out + (size_t)BB * SS * DD;
    float* vout = kout + (size_t)BB * HH * SS * HD;

    float *xr, *war, *wt, *ga, *kr, *vr;
    cudaGetSymbolAddress((void**)&xr, g_xr);
    cudaGetSymbolAddress((void**)&war, g_war);
    cudaGetSymbolAddress((void**)&wt, g_wt);
    cudaGetSymbolAddress((void**)&ga, g_a);
    cudaGetSymbolAddress((void**)&kr, g_kr);
    cudaGetSymbolAddress((void**)&vr, g_vr);

    cudaFuncSetAttribute(mma_gemm<0>, cudaFuncAttributeMaxDynamicSharedMemorySize, GEMM_SMEM);
    cudaFuncSetAttribute(mma_gemm<1>, cudaFuncAttributeMaxDynamicSharedMemorySize, GEMM_SMEM);
    cudaFuncSetAttribute(attn_tc, cudaFuncAttributeMaxDynamicSharedMemorySize, ATT_SMEM);

    // Pre-round GEMM inputs to tf32
    round_kernel<<<1024, 256>>>((const float4*)x, (float4*)xr, BB * SS * DD / 4);
    round_kernel<<<1024, 256>>>((const float4*)w_attn, (float4*)war, 3 * DD * DD / 4);
    transpose_round_kernel<<<dim3(32, 32), dim3(32, 8)>>>(w_proj, wt);

    // QKV GEMM: q(rounded)->g_q, k/v exact->present + rounded->g_kr/g_vr
    mma_gemm<1><<<dim3(3 * DD / 128, BB * SS / 128), 256, GEMM_SMEM>>>(
        xr, war, b_attn, nullptr, kout, vout);

    // Tensor-core flash attention -> g_a (tf32-rounded)
    attn_tc<<<dim3(BB * HH, SS / 128), 256, ATT_SMEM>>>(kr, vr);

    // Proj GEMM -> out
    mma_gemm<0><<<dim3(DD / 128, BB * SS / 128), 256, GEMM_SMEM>>>(
        ga, wt, b_proj, out, nullptr, nullptr);
}

// round 8
// speedup vs baseline: 1.1308x; 1.0556x over previous
#include <cuda_runtime.h>
#include <cstdint>

#define BB 4
#define SS 2048
#define DD 1024
#define HH 16
#define HD 64

// Scratch (allocation-free)
__device__ float g_q[(size_t)BB * HH * SS * HD];   // q [B,H,S,hd] (tf32-rounded)
__device__ float g_a[(size_t)BB * SS * DD];        // attention out (tf32-rounded)
__device__ float g_xr[(size_t)BB * SS * DD];       // x rounded to tf32
__device__ float g_war[(size_t)3 * DD * DD];       // w_attn rounded to tf32
__device__ float g_wt[(size_t)DD * DD];            // w_proj^T rounded to tf32
__device__ float g_kr[(size_t)BB * HH * SS * HD];  // k rounded (attention input)
__device__ float g_vr[(size_t)BB * HH * SS * HD];  // v rounded (attention input)

// ---------------------------------------------------------------------------
__device__ __forceinline__ uint32_t smem_u32(const void* p) {
    uint32_t a;
    asm("{ .reg .u64 t; cvta.to.shared.u64 t, %1; cvt.u32.u64 %0, t; }"
        : "=r"(a) : "l"(p));
    return a;
}
__device__ __forceinline__ uint32_t f2tf(float f) {
    uint32_t u;
    asm("cvt.rna.tf32.f32 %0, %1;" : "=r"(u) : "f"(f));
    return u;
}
__device__ __forceinline__ void cp_async16(uint32_t dst, const void* src) {
    asm volatile("cp.async.cg.shared.global [%0], [%1], 16;" :: "r"(dst), "l"(src));
}
#define CP_COMMIT() asm volatile("cp.async.commit_group;" ::: "memory")
#define CP_WAIT(n)  asm volatile("cp.async.wait_group %0;" :: "n"(n) : "memory")

__device__ __forceinline__ void mma_tf32(float* c, const uint32_t* a, const uint32_t* b) {
    asm volatile(
        "mma.sync.aligned.m16n8k8.row.col.f32.tf32.tf32.f32 "
        "{%0,%1,%2,%3}, {%4,%5,%6,%7}, {%8,%9}, {%0,%1,%2,%3};"
        : "+f"(c[0]), "+f"(c[1]), "+f"(c[2]), "+f"(c[3])
        : "r"(a[0]), "r"(a[1]), "r"(a[2]), "r"(a[3]), "r"(b[0]), "r"(b[1]));
}

// ---------------------------------------------------------------------------
// Elementwise round-to-tf32
// ---------------------------------------------------------------------------
__global__ __launch_bounds__(256) void round_kernel(
    const float4* __restrict__ in, float4* __restrict__ out, int n4)
{
    int i = blockIdx.x * blockDim.x + threadIdx.x;
    int stride = gridDim.x * blockDim.x;
    for (; i < n4; i += stride) {
        float4 v = in[i];
        float4 o;
        o.x = __uint_as_float(f2tf(v.x));
        o.y = __uint_as_float(f2tf(v.y));
        o.z = __uint_as_float(f2tf(v.z));
        o.w = __uint_as_float(f2tf(v.w));
        out[i] = o;
    }
}

__global__ __launch_bounds__(256) void transpose_round_kernel(
    const float* __restrict__ in, float* __restrict__ out)
{
    __shared__ float t[32][33];
    const int tx = threadIdx.x, ty = threadIdx.y;
    const int k0 = blockIdx.y * 32;
    const int n0 = blockIdx.x * 32;
#pragma unroll
    for (int i = ty; i < 32; i += 8)
        t[i][tx] = in[(size_t)(k0 + i) * DD + n0 + tx];
    __syncthreads();
#pragma unroll
    for (int i = ty; i < 32; i += 8)
        out[(size_t)(n0 + i) * DD + k0 + tx] = __uint_as_float(f2tf(t[tx][i]));
}

// ---------------------------------------------------------------------------
// tf32 mma.sync GEMM: 128x128 CTA tile, 32x64 warp tile, BK=32,
// 3-stage cp.async pipeline, ONE barrier per chunk, 2 CTAs/SM.
// MODE 0: C -> out0. MODE 1: q->g_q (rounded), k->out1 + g_kr, v->out2 + g_vr.
// ---------------------------------------------------------------------------
#define KDIM 1024
#define NCHUNK (KDIM / 32)
#define STG_F 9216                 // (128+128)*36 floats per stage
#define ROWSTRIDE 36
#define GEMM_SMEM (3 * STG_F * 4)  // 110592 bytes

template <int MODE>
__global__ __launch_bounds__(256, 2) void mma_gemm(
    const float* __restrict__ A, const float* __restrict__ Bm,
    const float* __restrict__ bias,
    float* __restrict__ out0, float* __restrict__ out1, float* __restrict__ out2)
{
    extern __shared__ float sm[];
    const uint32_t sbase = smem_u32(sm);
    const int tid = threadIdx.x;
    const int wid = tid >> 5;
    const int lane = tid & 31;
    const int g = lane >> 2;
    const int tig = lane & 3;
    const int m0 = blockIdx.y * 128;
    const int n0 = blockIdx.x * 128;
    const int wm = (wid & 3) * 32;
    const int wn = (wid >> 2) * 64;

    float c[2][8][4];
#pragma unroll
    for (int i = 0; i < 2; i++)
#pragma unroll
        for (int j = 0; j < 8; j++)
#pragma unroll
            for (int k = 0; k < 4; k++) c[i][j][k] = 0.f;

    const int lrow = tid >> 3;
    const int lcol = (tid & 7) * 4;
    const float* Abase = A + (size_t)m0 * KDIM;
    const float* Bbase = Bm + (size_t)n0 * KDIM;

#define ISSUE(chunk) do {                                                           \
    const int _k0 = (chunk) * 32;                                                   \
    const uint32_t _as = sbase + (uint32_t)((chunk) % 3) * STG_F * 4;               \
    const uint32_t _bs = _as + 4608 * 4;                                            \
    _Pragma("unroll")                                                               \
    for (int _i = 0; _i < 4; _i++) {                                                \
        const int _r = lrow + _i * 32;                                              \
        cp_async16(_as + (uint32_t)(_r * ROWSTRIDE + lcol) * 4,                     \
                   Abase + (size_t)_r * KDIM + _k0 + lcol);                         \
        cp_async16(_bs + (uint32_t)(_r * ROWSTRIDE + lcol) * 4,                     \
                   Bbase + (size_t)_r * KDIM + _k0 + lcol);                         \
    }                                                                               \
    CP_COMMIT();                                                                    \
} while (0)

    ISSUE(0);
    ISSUE(1);

    for (int ch = 0; ch < NCHUNK; ch++) {
        // stage ch%3 arrived?
        if (ch + 1 < NCHUNK) { CP_WAIT(1); } else { CP_WAIT(0); }
        __syncthreads();   // publish stage ch%3; all readers of stage (ch+2)%3 are past

        // refill the stage freed last iteration; overlaps this chunk's compute
        if (ch + 2 < NCHUNK) ISSUE(ch + 2);

        const float* As_ = sm + (ch % 3) * STG_F;
        const float* Bs_ = As_ + 4608;
#pragma unroll
        for (int ks = 0; ks < 4; ks++) {
            const int kc = ks * 8 + tig;
            uint32_t af[2][4], bf[8][2];
#pragma unroll
            for (int mt = 0; mt < 2; mt++) {
                const int r = wm + mt * 16 + g;
                af[mt][0] = __float_as_uint(As_[r * ROWSTRIDE + kc]);
                af[mt][1] = __float_as_uint(As_[(r + 8) * ROWSTRIDE + kc]);
                af[mt][2] = __float_as_uint(As_[r * ROWSTRIDE + kc + 4]);
                af[mt][3] = __float_as_uint(As_[(r + 8) * ROWSTRIDE + kc + 4]);
            }
#pragma unroll
            for (int nt = 0; nt < 8; nt++) {
                const int rn = wn + nt * 8 + g;
                bf[nt][0] = __float_as_uint(Bs_[rn * ROWSTRIDE + kc]);
                bf[nt][1] = __float_as_uint(Bs_[rn * ROWSTRIDE + kc + 4]);
            }
#pragma unroll
            for (int mt = 0; mt < 2; mt++)
#pragma unroll
                for (int nt = 0; nt < 8; nt++)
                    mma_tf32(c[mt][nt], af[mt], bf[nt]);
        }
    }

#pragma unroll
    for (int mt = 0; mt < 2; mt++) {
        const int row0 = m0 + wm + mt * 16 + g;
        const int row1 = row0 + 8;
#pragma unroll
        for (int nt = 0; nt < 8; nt++) {
            const int n = n0 + wn + nt * 8 + 2 * tig;
            const float2 bv = *(const float2*)(bias + n);
            float2 v0, v1;
            v0.x = c[mt][nt][0] + bv.x; v0.y = c[mt][nt][1] + bv.y;
            v1.x = c[mt][nt][2] + bv.x; v1.y = c[mt][nt][3] + bv.y;
            if (MODE == 0) {
                *(float2*)(out0 + (size_t)row0 * DD + n) = v0;
                *(float2*)(out0 + (size_t)row1 * DD + n) = v1;
            } else {
                const int part = n >> 10;
                const int hc = n & (DD - 1);
                const int h = hc >> 6;
                const int d = hc & 63;
                const int b0_ = row0 >> 11, s0_ = row0 & (SS - 1);
                const int b1_ = row1 >> 11, s1_ = row1 & (SS - 1);
                const size_t d0 = (((size_t)(b0_ * HH + h)) * SS + s0_) * HD + d;
                const size_t d1 = (((size_t)(b1_ * HH + h)) * SS + s1_) * HD + d;
                float2 r0v, r1v;
                r0v.x = __uint_as_float(f2tf(v0.x)); r0v.y = __uint_as_float(f2tf(v0.y));
                r1v.x = __uint_as_float(f2tf(v1.x)); r1v.y = __uint_as_float(f2tf(v1.y));
                if (part == 0) {
                    *(float2*)(g_q + d0) = r0v;
                    *(float2*)(g_q + d1) = r1v;
                } else if (part == 1) {
                    *(float2*)(out1 + d0) = v0;       // exact -> present
                    *(float2*)(out1 + d1) = v1;
                    *(float2*)(g_kr + d0) = r0v;      // rounded -> attention
                    *(float2*)(g_kr + d1) = r1v;
                } else {
                    *(float2*)(out2 + d0) = v0;
                    *(float2*)(out2 + d1) = v1;
                    *(float2*)(g_vr + d0) = r0v;
                    *(float2*)(g_vr + d1) = r1v;
                }
            }
        }
    }
}

// ---------------------------------------------------------------------------
// Tensor-core causal flash attention. Heaviest q-blocks first, ONE barrier
// per key tile, 2 CTAs/SM.
// CTA: 256 threads (8 warps), 128 queries. Key tiles of 64, cp.async x2 stages.
// ---------------------------------------------------------------------------
#define KSTR 76
#define PSTR 68
#define KVSTG 19456u                         // 64*76*4
#define AKS_OFF(s) ((uint32_t)(s) * KVSTG)
#define AVS_OFF(s) (2u * KVSTG + (uint32_t)(s) * KVSTG)
#define APS_OFF (4u * KVSTG)                 // 77824
#define ATT_SMEM (APS_OFF + 128u * PSTR * 4u)  // 112640 bytes

__global__ __launch_bounds__(256, 2) void attn_tc(
    const float* __restrict__ kr, const float* __restrict__ vr)
{
    extern __shared__ char smc[];
    float* smf = (float*)smc;
    const uint32_t sb = smem_u32(smc);
    const int tid = threadIdx.x;
    const int w = tid >> 5, lane = tid & 31;
    const int g = lane >> 2, tig = lane & 3;
    const int bh = blockIdx.x;
    const int qblk = (gridDim.y - 1) - blockIdx.y;   // big blocks first
    const int q0 = qblk * 128;
    const int tmax = 2 * qblk + 1;
    const float* kbase = kr + (size_t)bh * SS * HD;
    const float* vbase = vr + (size_t)bh * SS * HD;

#define AISSUE(t) do {                                                            \
    const int _st = (t) & 1;                                                      \
    const int _k0 = (t) * 64;                                                     \
    _Pragma("unroll")                                                             \
    for (int _i = 0; _i < 4; _i++) {                                              \
        const int _f = tid + 256 * _i;                                            \
        const int _r = _f >> 4;                                                   \
        const int _c = (_f & 15) << 2;                                            \
        cp_async16(sb + AKS_OFF(_st) + (uint32_t)(_r * KSTR + _c) * 4,            \
                   kbase + (size_t)(_k0 + _r) * HD + _c);                         \
        cp_async16(sb + AVS_OFF(_st) + (uint32_t)(_r * KSTR + _c) * 4,            \
                   vbase + (size_t)(_k0 + _r) * HD + _c);                         \
    }                                                                             \
    CP_COMMIT();                                                                  \
} while (0)

    {
        const float* qbase = g_q + ((size_t)bh * SS + q0) * HD;
#pragma unroll
        for (int i = 0; i < 8; i++) {
            const int f = tid + 256 * i;
            const int r = f >> 4;
            const int c = (f & 15) << 2;
            cp_async16(sb + APS_OFF + (uint32_t)(r * PSTR + c) * 4,
                       qbase + (size_t)r * HD + c);
        }
        CP_COMMIT();
    }
    AISSUE(0);
    CP_WAIT(1);            // Q staged
    __syncthreads();

    const int r0 = w * 16 + g;

    uint32_t qa[8][4];
    {
        const float* Q = smf + APS_OFF / 4;
#pragma unroll
        for (int kc = 0; kc < 8; kc++) {
            qa[kc][0] = __float_as_uint(Q[r0 * PSTR + kc * 8 + tig] * 0.125f);
            qa[kc][1] = __float_as_uint(Q[(r0 + 8) * PSTR + kc * 8 + tig] * 0.125f);
            qa[kc][2] = __float_as_uint(Q[r0 * PSTR + kc * 8 + tig + 4] * 0.125f);
            qa[kc][3] = __float_as_uint(Q[(r0 + 8) * PSTR + kc * 8 + tig + 4] * 0.125f);
        }
    }

    float o[8][4];
#pragma unroll
    for (int i = 0; i < 8; i++)
#pragma unroll
        for (int j = 0; j < 4; j++) o[i][j] = 0.f;
    float m0 = -1e30f, m1 = -1e30f, l0 = 0.f, l1 = 0.f;

    for (int t = 0; t <= tmax; t++) {
        const int st = t & 1;
        CP_WAIT(0);        // K/V tile t arrived
        __syncthreads();   // publish tile t; all readers of stage st^1 are past
        if (t < tmax) AISSUE(t + 1);   // refill freed stage; overlaps compute

        float s[8][4];
#pragma unroll
        for (int i = 0; i < 8; i++)
#pragma unroll
            for (int j = 0; j < 4; j++) s[i][j] = 0.f;

        const float* Ks = smf + AKS_OFF(st) / 4;
#pragma unroll
        for (int kc = 0; kc < 8; kc++) {
            uint32_t kb[8][2];
#pragma unroll
            for (int nt = 0; nt < 8; nt++) {
                kb[nt][0] = __float_as_uint(Ks[(8 * nt + g) * KSTR + 8 * kc + tig]);
                kb[nt][1] = __float_as_uint(Ks[(8 * nt + g) * KSTR + 8 * kc + tig + 4]);
            }
#pragma unroll
            for (int nt = 0; nt < 8; nt++)
                mma_tf32(s[nt], qa[kc], kb[nt]);
        }

        if (t >= 2 * qblk) {
            const int qg0 = q0 + r0;
            const int qg1 = qg0 + 8;
            const int kb0 = t * 64;
#pragma unroll
            for (int nt = 0; nt < 8; nt++) {
                const int col = kb0 + 8 * nt + 2 * tig;
                if (col > qg0)     s[nt][0] = -1e30f;
                if (col + 1 > qg0) s[nt][1] = -1e30f;
                if (col > qg1)     s[nt][2] = -1e30f;
                if (col + 1 > qg1) s[nt][3] = -1e30f;
            }
        }

        float mx0 = -1e30f, mx1 = -1e30f;
#pragma unroll
        for (int nt = 0; nt < 8; nt++) {
            mx0 = fmaxf(mx0, fmaxf(s[nt][0], s[nt][1]));
            mx1 = fmaxf(mx1, fmaxf(s[nt][2], s[nt][3]));
        }
        mx0 = fmaxf(mx0, __shfl_xor_sync(0xffffffffu, mx0, 1));
        mx0 = fmaxf(mx0, __shfl_xor_sync(0xffffffffu, mx0, 2));
        mx1 = fmaxf(mx1, __shfl_xor_sync(0xffffffffu, mx1, 1));
        mx1 = fmaxf(mx1, __shfl_xor_sync(0xffffffffu, mx1, 2));

        const float mn0 = fmaxf(m0, mx0);
        const float mn1 = fmaxf(m1, mx1);
        const float a0 = __expf(m0 - mn0);
        const float a1 = __expf(m1 - mn1);
        m0 = mn0; m1 = mn1;
        l0 *= a0; l1 *= a1;
#pragma unroll
        for (int nt = 0; nt < 8; nt++) {
            o[nt][0] *= a0; o[nt][1] *= a0;
            o[nt][2] *= a1; o[nt][3] *= a1;
        }

        float* Ps = smf + APS_OFF / 4;
        float rs0 = 0.f, rs1 = 0.f;
#pragma unroll
        for (int nt = 0; nt < 8; nt++) {
            const float p0 = __expf(s[nt][0] - mn0);
            const float p1 = __expf(s[nt][1] - mn0);
            const float p2 = __expf(s[nt][2] - mn1);
            const float p3 = __expf(s[nt][3] - mn1);
            rs0 += p0 + p1;
            rs1 += p2 + p3;
            float2 w0, w1;
            w0.x = __uint_as_float(f2tf(p0)); w0.y = __uint_as_float(f2tf(p1));
            w1.x = __uint_as_float(f2tf(p2)); w1.y = __uint_as_float(f2tf(p3));
            *(float2*)(Ps + r0 * PSTR + 8 * nt + 2 * tig) = w0;
            *(float2*)(Ps + (r0 + 8) * PSTR + 8 * nt + 2 * tig) = w1;
        }
        rs0 += __shfl_xor_sync(0xffffffffu, rs0, 1);
        rs0 += __shfl_xor_sync(0xffffffffu, rs0, 2);
        rs1 += __shfl_xor_sync(0xffffffffu, rs1, 1);
        rs1 += __shfl_xor_sync(0xffffffffu, rs1, 2);
        l0 += rs0; l1 += rs1;

        __syncwarp();      // P rows are warp-private

        const float* Vs = smf + AVS_OFF(st) / 4;
#pragma unroll
        for (int kc = 0; kc < 8; kc++) {
            uint32_t af[4];
            af[0] = __float_as_uint(Ps[r0 * PSTR + 8 * kc + tig]);
            af[1] = __float_as_uint(Ps[(r0 + 8) * PSTR + 8 * kc + tig]);
            af[2] = __float_as_uint(Ps[r0 * PSTR + 8 * kc + tig + 4]);
            af[3] = __float_as_uint(Ps[(r0 + 8) * PSTR + 8 * kc + tig + 4]);
            uint32_t vb[8][2];
#pragma unroll
            for (int nt = 0; nt < 8; nt++) {
                vb[nt][0] = __float_as_uint(Vs[(8 * kc + tig) * KSTR + 8 * nt + g]);
                vb[nt][1] = __float_as_uint(Vs[(8 * kc + tig + 4) * KSTR + 8 * nt + g]);
            }
#pragma unroll
            for (int nt = 0; nt < 8; nt++)
                mma_tf32(o[nt], af, vb[nt]);
        }
    }

    const float inv0 = 1.0f / l0;
    const float inv1 = 1.0f / l1;
    const int b = bh >> 4, h = bh & 15;
    const size_t base0 = ((size_t)b * SS + q0 + r0) * DD + h * 64;
    const size_t base1 = ((size_t)b * SS + q0 + r0 + 8) * DD + h * 64;
#pragma unroll
    for (int nt = 0; nt < 8; nt++) {
        const int col = 8 * nt + 2 * tig;
        float2 w0, w1;
        w0.x = __uint_as_float(f2tf(o[nt][0] * inv0));
        w0.y = __uint_as_float(f2tf(o[nt][1] * inv0));
        w1.x = __uint_as_float(f2tf(o[nt][2] * inv1));
        w1.y = __uint_as_float(f2tf(o[nt][3] * inv1));
        *(float2*)(g_a + base0 + col) = w0;
        *(float2*)(g_a + base1 + col) = w1;
    }
}

// ---------------------------------------------------------------------------
extern "C" void kernel_launch(void* const* d_in, const int* in_sizes, int n_in,
                              void* d_out, int out_size)
{
    const float* x      = (const float*)d_in[0];
    const float* w_attn = (const float*)d_in[1];
    const float* b_attn = (const float*)d_in[2];
    const float* w_proj = (const float*)d_in[3];
    const float* b_proj = (const float*)d_in[4];

    float* out  = (float*)d_out;
    float* kout = out + (size_t)BB * SS * DD;
    float* vout = kout + (size_t)BB * HH * SS * HD;

    float *xr, *war, *wt, *ga, *kr, *vr;
    cudaGetSymbolAddress((void**)&xr, g_xr);
    cudaGetSymbolAddress((void**)&war, g_war);
    cudaGetSymbolAddress((void**)&wt, g_wt);
    cudaGetSymbolAddress((void**)&ga, g_a);
    cudaGetSymbolAddress((void**)&kr, g_kr);
    cudaGetSymbolAddress((void**)&vr, g_vr);

    cudaFuncSetAttribute(mma_gemm<0>, cudaFuncAttributeMaxDynamicSharedMemorySize, GEMM_SMEM);
    cudaFuncSetAttribute(mma_gemm<1>, cudaFuncAttributeMaxDynamicSharedMemorySize, GEMM_SMEM);
    cudaFuncSetAttribute(attn_tc, cudaFuncAttributeMaxDynamicSharedMemorySize, ATT_SMEM);

    // Pre-round GEMM inputs to tf32
    round_kernel<<<1024, 256>>>((const float4*)x, (float4*)xr, BB * SS * DD / 4);
    round_kernel<<<1024, 256>>>((const float4*)w_attn, (float4*)war, 3 * DD * DD / 4);
    transpose_round_kernel<<<dim3(32, 32), dim3(32, 8)>>>(w_proj, wt);

    // QKV GEMM: q(rounded)->g_q, k/v exact->present + rounded->g_kr/g_vr
    mma_gemm<1><<<dim3(3 * DD / 128, BB * SS / 128), 256, GEMM_SMEM>>>(
        xr, war, b_attn, nullptr, kout, vout);

    // Tensor-core flash attention -> g_a (tf32-rounded)
    attn_tc<<<dim3(BB * HH, SS / 128), 256, ATT_SMEM>>>(kr, vr);

    // Proj GEMM -> out
    mma_gemm<0><<<dim3(DD / 128, BB * SS / 128), 256, GEMM_SMEM>>>(
        ga, wt, b_proj, out, nullptr, nullptr);
}

// round 9
// speedup vs baseline: 1.3316x; 1.1775x over previous
#include <cuda_runtime.h>
#include <cuda_fp16.h>
#include <cstdint>

#define BB 4
#define SS 2048
#define DD 1024
#define HH 16
#define HD 64

// Scratch (allocation-free)
__device__ float  g_q[(size_t)BB * HH * SS * HD];   // q (tf32-rounded, attention input)
__device__ float  g_kr[(size_t)BB * HH * SS * HD];  // k (tf32-rounded, attention input)
__device__ float  g_vr[(size_t)BB * HH * SS * HD];  // v (tf32-rounded, attention input)
__device__ __half g_a[(size_t)BB * SS * DD];        // attention out (fp16, proj input)
__device__ __half g_xh[(size_t)BB * SS * DD];       // x in fp16
__device__ __half g_wah[(size_t)3 * DD * DD];       // w_attn in fp16
__device__ __half g_wth[(size_t)DD * DD];           // w_proj^T in fp16

// ---------------------------------------------------------------------------
__device__ __forceinline__ uint32_t smem_u32(const void* p) {
    uint32_t a;
    asm("{ .reg .u64 t; cvta.to.shared.u64 t, %1; cvt.u32.u64 %0, t; }"
        : "=r"(a) : "l"(p));
    return a;
}
__device__ __forceinline__ uint32_t f2tf(float f) {
    uint32_t u;
    asm("cvt.rna.tf32.f32 %0, %1;" : "=r"(u) : "f"(f));
    return u;
}
__device__ __forceinline__ void cp_async16(uint32_t dst, const void* src) {
    asm volatile("cp.async.cg.shared.global [%0], [%1], 16;" :: "r"(dst), "l"(src));
}
#define CP_COMMIT() asm volatile("cp.async.commit_group;" ::: "memory")
#define CP_WAIT(n)  asm volatile("cp.async.wait_group %0;" :: "n"(n) : "memory")

__device__ __forceinline__ void mma_tf32(float* c, const uint32_t* a, const uint32_t* b) {
    asm volatile(
        "mma.sync.aligned.m16n8k8.row.col.f32.tf32.tf32.f32 "
        "{%0,%1,%2,%3}, {%4,%5,%6,%7}, {%8,%9}, {%0,%1,%2,%3};"
        : "+f"(c[0]), "+f"(c[1]), "+f"(c[2]), "+f"(c[3])
        : "r"(a[0]), "r"(a[1]), "r"(a[2]), "r"(a[3]), "r"(b[0]), "r"(b[1]));
}
__device__ __forceinline__ void mma_f16(float* c, const uint32_t* a, const uint32_t* b) {
    asm volatile(
        "mma.sync.aligned.m16n8k16.row.col.f32.f16.f16.f32 "
        "{%0,%1,%2,%3}, {%4,%5,%6,%7}, {%8,%9}, {%0,%1,%2,%3};"
        : "+f"(c[0]), "+f"(c[1]), "+f"(c[2]), "+f"(c[3])
        : "r"(a[0]), "r"(a[1]), "r"(a[2]), "r"(a[3]), "r"(b[0]), "r"(b[1]));
}

// ---------------------------------------------------------------------------
// fp32 -> fp16 conversion (float4 -> 8 bytes)
// ---------------------------------------------------------------------------
__global__ __launch_bounds__(256) void round_h_kernel(
    const float4* __restrict__ in, uint2* __restrict__ out, int n4)
{
    int i = blockIdx.x * blockDim.x + threadIdx.x;
    int stride = gridDim.x * blockDim.x;
    for (; i < n4; i += stride) {
        float4 v = in[i];
        __half2 h0 = __floats2half2_rn(v.x, v.y);
        __half2 h1 = __floats2half2_rn(v.z, v.w);
        uint2 o;
        o.x = *(uint32_t*)&h0;
        o.y = *(uint32_t*)&h1;
        out[i] = o;
    }
}

// w_proj [K,N] -> g_wth [N,K] in fp16
__global__ __launch_bounds__(256) void transpose_round_h_kernel(
    const float* __restrict__ in, __half* __restrict__ out)
{
    __shared__ float t[32][33];
    const int tx = threadIdx.x, ty = threadIdx.y;
    const int k0 = blockIdx.y * 32;
    const int n0 = blockIdx.x * 32;
#pragma unroll
    for (int i = ty; i < 32; i += 8)
        t[i][tx] = in[(size_t)(k0 + i) * DD + n0 + tx];
    __syncthreads();
#pragma unroll
    for (int i = ty; i < 32; i += 8)
        out[(size_t)(n0 + i) * DD + k0 + tx] = __float2half_rn(t[tx][i]);
}

// ---------------------------------------------------------------------------
// fp16 mma.sync GEMM: 128x128 CTA tile, 32x64 warp tile, BK=64 halfs,
// 3-stage cp.async, ONE barrier per chunk, 2 CTAs/SM.
// C[m,n] = sum_k A[m,k]*B[n,k] + bias[n] (fp32 accum).
// MODE 0: C -> out0. MODE 1: q->g_q, k->out1 + g_kr, v->out2 + g_vr (tf32).
// ---------------------------------------------------------------------------
#define KDIM 1024
#define NCHUNK 16                   // 1024 / 64
#define HSTR 72                     // halfs per smem row (144 B, conflict-free)
#define STG_H (256 * HSTR)          // halfs per stage (A 128 rows + B 128 rows)
#define STG_BYTES (STG_H * 2)       // 36864
#define GEMM_SMEM (3 * STG_BYTES)   // 110592

template <int MODE>
__global__ __launch_bounds__(256, 2) void mma_gemm_h(
    const __half* __restrict__ A, const __half* __restrict__ Bm,
    const float* __restrict__ bias,
    float* __restrict__ out0, float* __restrict__ out1, float* __restrict__ out2)
{
    extern __shared__ __half smh[];
    const uint32_t sbase = smem_u32(smh);
    const int tid = threadIdx.x;
    const int wid = tid >> 5;
    const int lane = tid & 31;
    const int g = lane >> 2;
    const int tig = lane & 3;
    const int m0 = blockIdx.y * 128;
    const int n0 = blockIdx.x * 128;
    const int wm = (wid & 3) * 32;
    const int wn = (wid >> 2) * 64;

    float c[2][8][4];
#pragma unroll
    for (int i = 0; i < 2; i++)
#pragma unroll
        for (int j = 0; j < 8; j++)
#pragma unroll
            for (int k = 0; k < 4; k++) c[i][j][k] = 0.f;

    const int lr = tid >> 1;            // 0..127
    const int lcb = (tid & 1) * 64;     // byte col 0 or 64 within 128-B chunk row
    const char* Agc = (const char*)(A + (size_t)(m0 + lr) * KDIM) + lcb;
    const char* Bgc = (const char*)(Bm + (size_t)(n0 + lr) * KDIM) + lcb;

#define ISSUE(chunk) do {                                                           \
    const uint32_t _as = sbase + (uint32_t)((chunk) % 3) * STG_BYTES;               \
    const uint32_t _bs = _as + 128u * 144u;                                         \
    const int _kb = (chunk) * 128;                                                  \
    _Pragma("unroll")                                                               \
    for (int _i = 0; _i < 4; _i++)                                                  \
        cp_async16(_as + (uint32_t)(lr * 144 + lcb + _i * 16), Agc + _kb + _i * 16);\
    _Pragma("unroll")                                                               \
    for (int _i = 0; _i < 4; _i++)                                                  \
        cp_async16(_bs + (uint32_t)(lr * 144 + lcb + _i * 16), Bgc + _kb + _i * 16);\
    CP_COMMIT();                                                                    \
} while (0)

    ISSUE(0);
    ISSUE(1);

    for (int ch = 0; ch < NCHUNK; ch++) {
        if (ch + 1 < NCHUNK) { CP_WAIT(1); } else { CP_WAIT(0); }
        __syncthreads();     // publish stage ch%3; readers of stage (ch+2)%3 past
        if (ch + 2 < NCHUNK) ISSUE(ch + 2);

        const __half* As_ = smh + (size_t)(ch % 3) * STG_H;
        const __half* Bs_ = As_ + 128 * HSTR;
#pragma unroll
        for (int ks = 0; ks < 4; ks++) {
            const int kc = ks * 16 + 2 * tig;
            uint32_t af[2][4], bf[8][2];
#pragma unroll
            for (int mt = 0; mt < 2; mt++) {
                const int r = wm + mt * 16 + g;
                af[mt][0] = *(const uint32_t*)(As_ + r * HSTR + kc);
                af[mt][1] = *(const uint32_t*)(As_ + (r + 8) * HSTR + kc);
                af[mt][2] = *(const uint32_t*)(As_ + r * HSTR + kc + 8);
                af[mt][3] = *(const uint32_t*)(As_ + (r + 8) * HSTR + kc + 8);
            }
#pragma unroll
            for (int nt = 0; nt < 8; nt++) {
                const int rn = wn + nt * 8 + g;
                bf[nt][0] = *(const uint32_t*)(Bs_ + rn * HSTR + kc);
                bf[nt][1] = *(const uint32_t*)(Bs_ + rn * HSTR + kc + 8);
            }
#pragma unroll
            for (int mt = 0; mt < 2; mt++)
#pragma unroll
                for (int nt = 0; nt < 8; nt++)
                    mma_f16(c[mt][nt], af[mt], bf[nt]);
        }
    }

#pragma unroll
    for (int mt = 0; mt < 2; mt++) {
        const int row0 = m0 + wm + mt * 16 + g;
        const int row1 = row0 + 8;
#pragma unroll
        for (int nt = 0; nt < 8; nt++) {
            const int n = n0 + wn + nt * 8 + 2 * tig;
            const float2 bv = *(const float2*)(bias + n);
            float2 v0, v1;
            v0.x = c[mt][nt][0] + bv.x; v0.y = c[mt][nt][1] + bv.y;
            v1.x = c[mt][nt][2] + bv.x; v1.y = c[mt][nt][3] + bv.y;
            if (MODE == 0) {
                *(float2*)(out0 + (size_t)row0 * DD + n) = v0;
                *(float2*)(out0 + (size_t)row1 * DD + n) = v1;
            } else {
                const int part = n >> 10;
                const int hc = n & (DD - 1);
                const int h = hc >> 6;
                const int d = hc & 63;
                const int b0_ = row0 >> 11, s0_ = row0 & (SS - 1);
                const int b1_ = row1 >> 11, s1_ = row1 & (SS - 1);
                const size_t d0 = (((size_t)(b0_ * HH + h)) * SS + s0_) * HD + d;
                const size_t d1 = (((size_t)(b1_ * HH + h)) * SS + s1_) * HD + d;
                float2 r0v, r1v;
                r0v.x = __uint_as_float(f2tf(v0.x)); r0v.y = __uint_as_float(f2tf(v0.y));
                r1v.x = __uint_as_float(f2tf(v1.x)); r1v.y = __uint_as_float(f2tf(v1.y));
                if (part == 0) {
                    *(float2*)(g_q + d0) = r0v;
                    *(float2*)(g_q + d1) = r1v;
                } else if (part == 1) {
                    *(float2*)(out1 + d0) = v0;       // exact -> present
                    *(float2*)(out1 + d1) = v1;
                    *(float2*)(g_kr + d0) = r0v;      // tf32-rounded -> attention
                    *(float2*)(g_kr + d1) = r1v;
                } else {
                    *(float2*)(out2 + d0) = v0;
                    *(float2*)(out2 + d1) = v1;
                    *(float2*)(g_vr + d0) = r0v;
                    *(float2*)(g_vr + d1) = r1v;
                }
            }
        }
    }
}

// ---------------------------------------------------------------------------
// Tensor-core causal flash attention (tf32). Heaviest q-blocks first,
// one barrier per key tile, fp16 output for the proj GEMM.
// ---------------------------------------------------------------------------
#define KSTR 76
#define PSTR 68
#define KVSTG 19456u                         // 64*76*4
#define AKS_OFF(s) ((uint32_t)(s) * KVSTG)
#define AVS_OFF(s) (2u * KVSTG + (uint32_t)(s) * KVSTG)
#define APS_OFF (4u * KVSTG)                 // 77824
#define ATT_SMEM (APS_OFF + 128u * PSTR * 4u)  // 112640 bytes

__global__ __launch_bounds__(256, 2) void attn_tc(
    const float* __restrict__ kr, const float* __restrict__ vr)
{
    extern __shared__ char smc[];
    float* smf = (float*)smc;
    const uint32_t sb = smem_u32(smc);
    const int tid = threadIdx.x;
    const int w = tid >> 5, lane = tid & 31;
    const int g = lane >> 2, tig = lane & 3;
    const int bh = blockIdx.x;
    const int qblk = (gridDim.y - 1) - blockIdx.y;   // big blocks first
    const int q0 = qblk * 128;
    const int tmax = 2 * qblk + 1;
    const float* kbase = kr + (size_t)bh * SS * HD;
    const float* vbase = vr + (size_t)bh * SS * HD;

#define AISSUE(t) do {                                                            \
    const int _st = (t) & 1;                                                      \
    const int _k0 = (t) * 64;                                                     \
    _Pragma("unroll")                                                             \
    for (int _i = 0; _i < 4; _i++) {                                              \
        const int _f = tid + 256 * _i;                                            \
        const int _r = _f >> 4;                                                   \
        const int _c = (_f & 15) << 2;                                            \
        cp_async16(sb + AKS_OFF(_st) + (uint32_t)(_r * KSTR + _c) * 4,            \
                   kbase + (size_t)(_k0 + _r) * HD + _c);                         \
        cp_async16(sb + AVS_OFF(_st) + (uint32_t)(_r * KSTR + _c) * 4,            \
                   vbase + (size_t)(_k0 + _r) * HD + _c);                         \
    }                                                                             \
    CP_COMMIT();                                                                  \
} while (0)

    {
        const float* qbase = g_q + ((size_t)bh * SS + q0) * HD;
#pragma unroll
        for (int i = 0; i < 8; i++) {
            const int f = tid + 256 * i;
            const int r = f >> 4;
            const int c = (f & 15) << 2;
            cp_async16(sb + APS_OFF + (uint32_t)(r * PSTR + c) * 4,
                       qbase + (size_t)r * HD + c);
        }
        CP_COMMIT();
    }
    AISSUE(0);
    CP_WAIT(1);
    __syncthreads();

    const int r0 = w * 16 + g;

    uint32_t qa[8][4];
    {
        const float* Q = smf + APS_OFF / 4;
#pragma unroll
        for (int kc = 0; kc < 8; kc++) {
            qa[kc][0] = __float_as_uint(Q[r0 * PSTR + kc * 8 + tig] * 0.125f);
            qa[kc][1] = __float_as_uint(Q[(r0 + 8) * PSTR + kc * 8 + tig] * 0.125f);
            qa[kc][2] = __float_as_uint(Q[r0 * PSTR + kc * 8 + tig + 4] * 0.125f);
            qa[kc][3] = __float_as_uint(Q[(r0 + 8) * PSTR + kc * 8 + tig + 4] * 0.125f);
        }
    }

    float o[8][4];
#pragma unroll
    for (int i = 0; i < 8; i++)
#pragma unroll
        for (int j = 0; j < 4; j++) o[i][j] = 0.f;
    float m0 = -1e30f, m1 = -1e30f, l0 = 0.f, l1 = 0.f;

    for (int t = 0; t <= tmax; t++) {
        const int st = t & 1;
        CP_WAIT(0);
        __syncthreads();
        if (t < tmax) AISSUE(t + 1);

        float s[8][4];
#pragma unroll
        for (int i = 0; i < 8; i++)
#pragma unroll
            for (int j = 0; j < 4; j++) s[i][j] = 0.f;

        const float* Ks = smf + AKS_OFF(st) / 4;
#pragma unroll
        for (int kc = 0; kc < 8; kc++) {
            uint32_t kb[8][2];
#pragma unroll
            for (int nt = 0; nt < 8; nt++) {
                kb[nt][0] = __float_as_uint(Ks[(8 * nt + g) * KSTR + 8 * kc + tig]);
                kb[nt][1] = __float_as_uint(Ks[(8 * nt + g) * KSTR + 8 * kc + tig + 4]);
            }
#pragma unroll
            for (int nt = 0; nt < 8; nt++)
                mma_tf32(s[nt], qa[kc], kb[nt]);
        }

        if (t >= 2 * qblk) {
            const int qg0 = q0 + r0;
            const int qg1 = qg0 + 8;
            const int kb0 = t * 64;
#pragma unroll
            for (int nt = 0; nt < 8; nt++) {
                const int col = kb0 + 8 * nt + 2 * tig;
                if (col > qg0)     s[nt][0] = -1e30f;
                if (col + 1 > qg0) s[nt][1] = -1e30f;
                if (col > qg1)     s[nt][2] = -1e30f;
                if (col + 1 > qg1) s[nt][3] = -1e30f;
            }
        }

        float mx0 = -1e30f, mx1 = -1e30f;
#pragma unroll
        for (int nt = 0; nt < 8; nt++) {
            mx0 = fmaxf(mx0, fmaxf(s[nt][0], s[nt][1]));
            mx1 = fmaxf(mx1, fmaxf(s[nt][2], s[nt][3]));
        }
        mx0 = fmaxf(mx0, __shfl_xor_sync(0xffffffffu, mx0, 1));
        mx0 = fmaxf(mx0, __shfl_xor_sync(0xffffffffu, mx0, 2));
        mx1 = fmaxf(mx1, __shfl_xor_sync(0xffffffffu, mx1, 1));
        mx1 = fmaxf(mx1, __shfl_xor_sync(0xffffffffu, mx1, 2));

        const float mn0 = fmaxf(m0, mx0);
        const float mn1 = fmaxf(m1, mx1);
        const float a0 = __expf(m0 - mn0);
        const float a1 = __expf(m1 - mn1);
        m0 = mn0; m1 = mn1;
        l0 *= a0; l1 *= a1;
#pragma unroll
        for (int nt = 0; nt < 8; nt++) {
            o[nt][0] *= a0; o[nt][1] *= a0;
            o[nt][2] *= a1; o[nt][3] *= a1;
        }

        float* Ps = smf + APS_OFF / 4;
        float rs0 = 0.f, rs1 = 0.f;
#pragma unroll
        for (int nt = 0; nt < 8; nt++) {
            const float p0 = __expf(s[nt][0] - mn0);
            const float p1 = __expf(s[nt][1] - mn0);
            const float p2 = __expf(s[nt][2] - mn1);
            const float p3 = __expf(s[nt][3] - mn1);
            rs0 += p0 + p1;
            rs1 += p2 + p3;
            float2 w0, w1;
            w0.x = __uint_as_float(f2tf(p0)); w0.y = __uint_as_float(f2tf(p1));
            w1.x = __uint_as_float(f2tf(p2)); w1.y = __uint_as_float(f2tf(p3));
            *(float2*)(Ps + r0 * PSTR + 8 * nt + 2 * tig) = w0;
            *(float2*)(Ps + (r0 + 8) * PSTR + 8 * nt + 2 * tig) = w1;
        }
        rs0 += __shfl_xor_sync(0xffffffffu, rs0, 1);
        rs0 += __shfl_xor_sync(0xffffffffu, rs0, 2);
        rs1 += __shfl_xor_sync(0xffffffffu, rs1, 1);
        rs1 += __shfl_xor_sync(0xffffffffu, rs1, 2);
        l0 += rs0; l1 += rs1;

        __syncwarp();

        const float* Vs = smf + AVS_OFF(st) / 4;
#pragma unroll
        for (int kc = 0; kc < 8; kc++) {
            uint32_t af[4];
            af[0] = __float_as_uint(Ps[r0 * PSTR + 8 * kc + tig]);
            af[1] = __float_as_uint(Ps[(r0 + 8) * PSTR + 8 * kc + tig]);
            af[2] = __float_as_uint(Ps[r0 * PSTR + 8 * kc + tig + 4]);
            af[3] = __float_as_uint(Ps[(r0 + 8) * PSTR + 8 * kc + tig + 4]);
            uint32_t vb[8][2];
#pragma unroll
            for (int nt = 0; nt < 8; nt++) {
                vb[nt][0] = __float_as_uint(Vs[(8 * kc + tig) * KSTR + 8 * nt + g]);
                vb[nt][1] = __float_as_uint(Vs[(8 * kc + tig + 4) * KSTR + 8 * nt + g]);
            }
#pragma unroll
            for (int nt = 0; nt < 8; nt++)
                mma_tf32(o[nt], af, vb[nt]);
        }
    }

    // epilogue: normalize, emit fp16 for proj GEMM
    const float inv0 = 1.0f / l0;
    const float inv1 = 1.0f / l1;
    const int b = bh >> 4, h = bh & 15;
    const size_t base0 = ((size_t)b * SS + q0 + r0) * DD + h * 64;
    const size_t base1 = ((size_t)b * SS + q0 + r0 + 8) * DD + h * 64;
#pragma unroll
    for (int nt = 0; nt < 8; nt++) {
        const int col = 8 * nt + 2 * tig;
        __half2 h0 = __floats2half2_rn(o[nt][0] * inv0, o[nt][1] * inv0);
        __half2 h1 = __floats2half2_rn(o[nt][2] * inv1, o[nt][3] * inv1);
        *(__half2*)(g_a + base0 + col) = h0;
        *(__half2*)(g_a + base1 + col) = h1;
    }
}

// ---------------------------------------------------------------------------
extern "C" void kernel_launch(void* const* d_in, const int* in_sizes, int n_in,
                              void* d_out, int out_size)
{
    const float* x      = (const float*)d_in[0];
    const float* w_attn = (const float*)d_in[1];
    const float* b_attn = (const float*)d_in[2];
    const float* w_proj = (const float*)d_in[3];
    const float* b_proj = (const float*)d_in[4];

    float* out  = (float*)d_out;
    float* kout = out + (size_t)BB * SS * DD;
    float* vout = kout + (size_t)BB * HH * SS * HD;

    __half *xh, *wah, *wth, *ah;
    float *kr, *vr;
    cudaGetSymbolAddress((void**)&xh, g_xh);
    cudaGetSymbolAddress((void**)&wah, g_wah);
    cudaGetSymbolAddress((void**)&wth, g_wth);
    cudaGetSymbolAddress((void**)&ah, g_a);
    cudaGetSymbolAddress((void**)&kr, g_kr);
    cudaGetSymbolAddress((void**)&vr, g_vr);

    cudaFuncSetAttribute(mma_gemm_h<0>, cudaFuncAttributeMaxDynamicSharedMemorySize, GEMM_SMEM);
    cudaFuncSetAttribute(mma_gemm_h<1>, cudaFuncAttributeMaxDynamicSharedMemorySize, GEMM_SMEM);
    cudaFuncSetAttribute(attn_tc, cudaFuncAttributeMaxDynamicSharedMemorySize, ATT_SMEM);

    // Convert GEMM inputs to fp16
    round_h_kernel<<<1024, 256>>>((const float4*)x, (uint2*)xh, BB * SS * DD / 4);
    round_h_kernel<<<1024, 256>>>((const float4*)w_attn, (uint2*)wah, 3 * DD * DD / 4);
    transpose_round_h_kernel<<<dim3(32, 32), dim3(32, 8)>>>(w_proj, wth);

    // QKV GEMM (fp16): q->g_q, k/v exact->present + tf32->g_kr/g_vr
    mma_gemm_h<1><<<dim3(3 * DD / 128, BB * SS / 128), 256, GEMM_SMEM>>>(
        xh, wah, b_attn, nullptr, kout, vout);

    // Tensor-core flash attention (tf32) -> g_a (fp16)
    attn_tc<<<dim3(BB * HH, SS / 128), 256, ATT_SMEM>>>(kr, vr);

    // Proj GEMM (fp16) -> out
    mma_gemm_h<0><<<dim3(DD / 128, BB * SS / 128), 256, GEMM_SMEM>>>(
        ah, wth, b_proj, out, nullptr, nullptr);
}

// round 10
// speedup vs baseline: 1.7810x; 1.3375x over previous
#include <cuda_runtime.h>
#include <cuda_fp16.h>
#include <cstdint>

#define BB 4
#define SS 2048
#define DD 1024
#define HH 16
#define HD 64

// Scratch (allocation-free)
__device__ __half g_qh[(size_t)BB * HH * SS * HD];  // q fp16, pre-scaled by 0.125
__device__ __half g_krh[(size_t)BB * HH * SS * HD]; // k fp16 (attention input)
__device__ __half g_vrh[(size_t)BB * HH * SS * HD]; // v fp16 (attention input)
__device__ __half g_a[(size_t)BB * SS * DD];        // attention out (fp16, proj input)
__device__ __half g_xh[(size_t)BB * SS * DD];       // x in fp16
__device__ __half g_wah[(size_t)3 * DD * DD];       // w_attn in fp16
__device__ __half g_wth[(size_t)DD * DD];           // w_proj^T in fp16

// ---------------------------------------------------------------------------
__device__ __forceinline__ uint32_t smem_u32(const void* p) {
    uint32_t a;
    asm("{ .reg .u64 t; cvta.to.shared.u64 t, %1; cvt.u32.u64 %0, t; }"
        : "=r"(a) : "l"(p));
    return a;
}
__device__ __forceinline__ void cp_async16(uint32_t dst, const void* src) {
    asm volatile("cp.async.cg.shared.global [%0], [%1], 16;" :: "r"(dst), "l"(src));
}
#define CP_COMMIT() asm volatile("cp.async.commit_group;" ::: "memory")
#define CP_WAIT(n)  asm volatile("cp.async.wait_group %0;" :: "n"(n) : "memory")

__device__ __forceinline__ void mma_f16(float* c, const uint32_t* a, const uint32_t* b) {
    asm volatile(
        "mma.sync.aligned.m16n8k16.row.col.f32.f16.f16.f32 "
        "{%0,%1,%2,%3}, {%4,%5,%6,%7}, {%8,%9}, {%0,%1,%2,%3};"
        : "+f"(c[0]), "+f"(c[1]), "+f"(c[2]), "+f"(c[3])
        : "r"(a[0]), "r"(a[1]), "r"(a[2]), "r"(a[3]), "r"(b[0]), "r"(b[1]));
}
#define LDSM_X4(r0, r1, r2, r3, addr) \
    asm volatile("ldmatrix.sync.aligned.m8n8.x4.shared.b16 {%0,%1,%2,%3}, [%4];" \
        : "=r"(r0), "=r"(r1), "=r"(r2), "=r"(r3) : "r"(addr))
#define LDSM_X4_T(r0, r1, r2, r3, addr) \
    asm volatile("ldmatrix.sync.aligned.m8n8.x4.trans.shared.b16 {%0,%1,%2,%3}, [%4];" \
        : "=r"(r0), "=r"(r1), "=r"(r2), "=r"(r3) : "r"(addr))

// ---------------------------------------------------------------------------
// fp32 -> fp16 conversion
// ---------------------------------------------------------------------------
__global__ __launch_bounds__(256) void round_h_kernel(
    const float4* __restrict__ in, uint2* __restrict__ out, int n4)
{
    int i = blockIdx.x * blockDim.x + threadIdx.x;
    int stride = gridDim.x * blockDim.x;
    for (; i < n4; i += stride) {
        float4 v = in[i];
        __half2 h0 = __floats2half2_rn(v.x, v.y);
        __half2 h1 = __floats2half2_rn(v.z, v.w);
        uint2 o;
        o.x = *(uint32_t*)&h0;
        o.y = *(uint32_t*)&h1;
        out[i] = o;
    }
}

__global__ __launch_bounds__(256) void transpose_round_h_kernel(
    const float* __restrict__ in, __half* __restrict__ out)
{
    __shared__ float t[32][33];
    const int tx = threadIdx.x, ty = threadIdx.y;
    const int k0 = blockIdx.y * 32;
    const int n0 = blockIdx.x * 32;
#pragma unroll
    for (int i = ty; i < 32; i += 8)
        t[i][tx] = in[(size_t)(k0 + i) * DD + n0 + tx];
    __syncthreads();
#pragma unroll
    for (int i = ty; i < 32; i += 8)
        out[(size_t)(n0 + i) * DD + k0 + tx] = __float2half_rn(t[tx][i]);
}

// ---------------------------------------------------------------------------
// fp16 mma.sync GEMM (unchanged structure): 128x128 tile, BK=64 halfs,
// 3 stages, one barrier per chunk, 2 CTAs/SM.
// MODE 0: C -> out0. MODE 1: q*0.125->g_qh, k->out1+g_krh, v->out2+g_vrh.
// ---------------------------------------------------------------------------
#define KDIM 1024
#define NCHUNK 16
#define HSTR 72
#define STG_H (256 * HSTR)
#define STG_BYTES (STG_H * 2)
#define GEMM_SMEM (3 * STG_BYTES)

template <int MODE>
__global__ __launch_bounds__(256, 2) void mma_gemm_h(
    const __half* __restrict__ A, const __half* __restrict__ Bm,
    const float* __restrict__ bias,
    float* __restrict__ out0, float* __restrict__ out1, float* __restrict__ out2)
{
    extern __shared__ __half smh[];
    const uint32_t sbase = smem_u32(smh);
    const int tid = threadIdx.x;
    const int wid = tid >> 5;
    const int lane = tid & 31;
    const int g = lane >> 2;
    const int tig = lane & 3;
    const int m0 = blockIdx.y * 128;
    const int n0 = blockIdx.x * 128;
    const int wm = (wid & 3) * 32;
    const int wn = (wid >> 2) * 64;

    float c[2][8][4];
#pragma unroll
    for (int i = 0; i < 2; i++)
#pragma unroll
        for (int j = 0; j < 8; j++)
#pragma unroll
            for (int k = 0; k < 4; k++) c[i][j][k] = 0.f;

    const int lr = tid >> 1;
    const int lcb = (tid & 1) * 64;
    const char* Agc = (const char*)(A + (size_t)(m0 + lr) * KDIM) + lcb;
    const char* Bgc = (const char*)(Bm + (size_t)(n0 + lr) * KDIM) + lcb;

#define ISSUE(chunk) do {                                                           \
    const uint32_t _as = sbase + (uint32_t)((chunk) % 3) * STG_BYTES;               \
    const uint32_t _bs = _as + 128u * 144u;                                         \
    const int _kb = (chunk) * 128;                                                  \
    _Pragma("unroll")                                                               \
    for (int _i = 0; _i < 4; _i++)                                                  \
        cp_async16(_as + (uint32_t)(lr * 144 + lcb + _i * 16), Agc + _kb + _i * 16);\
    _Pragma("unroll")                                                               \
    for (int _i = 0; _i < 4; _i++)                                                  \
        cp_async16(_bs + (uint32_t)(lr * 144 + lcb + _i * 16), Bgc + _kb + _i * 16);\
    CP_COMMIT();                                                                    \
} while (0)

    ISSUE(0);
    ISSUE(1);

    for (int ch = 0; ch < NCHUNK; ch++) {
        if (ch + 1 < NCHUNK) { CP_WAIT(1); } else { CP_WAIT(0); }
        __syncthreads();
        if (ch + 2 < NCHUNK) ISSUE(ch + 2);

        const __half* As_ = smh + (size_t)(ch % 3) * STG_H;
        const __half* Bs_ = As_ + 128 * HSTR;
#pragma unroll
        for (int ks = 0; ks < 4; ks++) {
            const int kc = ks * 16 + 2 * tig;
            uint32_t af[2][4], bf[8][2];
#pragma unroll
            for (int mt = 0; mt < 2; mt++) {
                const int r = wm + mt * 16 + g;
                af[mt][0] = *(const uint32_t*)(As_ + r * HSTR + kc);
                af[mt][1] = *(const uint32_t*)(As_ + (r + 8) * HSTR + kc);
                af[mt][2] = *(const uint32_t*)(As_ + r * HSTR + kc + 8);
                af[mt][3] = *(const uint32_t*)(As_ + (r + 8) * HSTR + kc + 8);
            }
#pragma unroll
            for (int nt = 0; nt < 8; nt++) {
                const int rn = wn + nt * 8 + g;
                bf[nt][0] = *(const uint32_t*)(Bs_ + rn * HSTR + kc);
                bf[nt][1] = *(const uint32_t*)(Bs_ + rn * HSTR + kc + 8);
            }
#pragma unroll
            for (int mt = 0; mt < 2; mt++)
#pragma unroll
                for (int nt = 0; nt < 8; nt++)
                    mma_f16(c[mt][nt], af[mt], bf[nt]);
        }
    }

#pragma unroll
    for (int mt = 0; mt < 2; mt++) {
        const int row0 = m0 + wm + mt * 16 + g;
        const int row1 = row0 + 8;
#pragma unroll
        for (int nt = 0; nt < 8; nt++) {
            const int n = n0 + wn + nt * 8 + 2 * tig;
            const float2 bv = *(const float2*)(bias + n);
            float2 v0, v1;
            v0.x = c[mt][nt][0] + bv.x; v0.y = c[mt][nt][1] + bv.y;
            v1.x = c[mt][nt][2] + bv.x; v1.y = c[mt][nt][3] + bv.y;
            if (MODE == 0) {
                *(float2*)(out0 + (size_t)row0 * DD + n) = v0;
                *(float2*)(out0 + (size_t)row1 * DD + n) = v1;
            } else {
                const int part = n >> 10;
                const int hc = n & (DD - 1);
                const int h = hc >> 6;
                const int d = hc & 63;
                const int b0_ = row0 >> 11, s0_ = row0 & (SS - 1);
                const int b1_ = row1 >> 11, s1_ = row1 & (SS - 1);
                const size_t d0 = (((size_t)(b0_ * HH + h)) * SS + s0_) * HD + d;
                const size_t d1 = (((size_t)(b1_ * HH + h)) * SS + s1_) * HD + d;
                if (part == 0) {
                    __half2 h0 = __floats2half2_rn(v0.x * 0.125f, v0.y * 0.125f);
                    __half2 h1 = __floats2half2_rn(v1.x * 0.125f, v1.y * 0.125f);
                    *(__half2*)(g_qh + d0) = h0;
                    *(__half2*)(g_qh + d1) = h1;
                } else if (part == 1) {
                    *(float2*)(out1 + d0) = v0;       // exact -> present
                    *(float2*)(out1 + d1) = v1;
                    *(__half2*)(g_krh + d0) = __floats2half2_rn(v0.x, v0.y);
                    *(__half2*)(g_krh + d1) = __floats2half2_rn(v1.x, v1.y);
                } else {
                    *(float2*)(out2 + d0) = v0;
                    *(float2*)(out2 + d1) = v1;
                    *(__half2*)(g_vrh + d0) = __floats2half2_rn(v0.x, v0.y);
                    *(__half2*)(g_vrh + d1) = __floats2half2_rn(v1.x, v1.y);
                }
            }
        }
    }
}

// ---------------------------------------------------------------------------
// fp16 tensor-core causal flash attention with ldmatrix.
// CTA: 256 threads (8 warps), 128 queries; key tiles of 64, 2 stages, 2 CTA/SM.
// Smem rows 144 B (72 halfs). K/V: [key][d]; Q/P share one [q][*] buffer.
// ---------------------------------------------------------------------------
#define HKOFF(s) ((uint32_t)(s) * 9216u)
#define HVOFF(s) (18432u + (uint32_t)(s) * 9216u)
#define HPOFF 36864u
#define ATT_SMEM 55296

__global__ __launch_bounds__(256, 2) void attn_h(
    const __half* __restrict__ qh, const __half* __restrict__ kh,
    const __half* __restrict__ vh)
{
    extern __shared__ char smc[];
    const uint32_t sb = smem_u32(smc);
    const int tid = threadIdx.x;
    const int w = tid >> 5, lane = tid & 31;
    const int g = lane >> 2, tig = lane & 3;
    const int bh = blockIdx.x;
    const int qblk = (gridDim.y - 1) - blockIdx.y;   // heaviest blocks first
    const int q0 = qblk * 128;
    const int tmax = 2 * qblk + 1;
    const __half* kbase = kh + (size_t)bh * SS * HD;
    const __half* vbase = vh + (size_t)bh * SS * HD;

#define HISSUE(t) do {                                                             \
    const int _st = (t) & 1;                                                       \
    const int _k0 = (t) * 64;                                                      \
    _Pragma("unroll")                                                              \
    for (int _i = 0; _i < 2; _i++) {                                               \
        const int _f = tid + 256 * _i;                                             \
        const int _r = _f >> 3;                                                    \
        const int _c = (_f & 7) * 16;                                              \
        cp_async16(sb + HKOFF(_st) + (uint32_t)(_r * 144 + _c),                    \
                   (const char*)(kbase + (size_t)(_k0 + _r) * HD) + _c);           \
        cp_async16(sb + HVOFF(_st) + (uint32_t)(_r * 144 + _c),                    \
                   (const char*)(vbase + (size_t)(_k0 + _r) * HD) + _c);           \
    }                                                                              \
    CP_COMMIT();                                                                   \
} while (0)

    // stage Q (128x64 fp16, already scaled by 0.125) into the P buffer
    {
        const __half* qb = qh + ((size_t)bh * SS + q0) * HD;
#pragma unroll
        for (int i = 0; i < 4; i++) {
            const int f = tid + 256 * i;
            const int r = f >> 3;
            const int c = (f & 7) * 16;
            cp_async16(sb + HPOFF + (uint32_t)(r * 144 + c),
                       (const char*)(qb + (size_t)r * HD) + c);
        }
        CP_COMMIT();
    }
    HISSUE(0);
    CP_WAIT(1);            // Q staged
    __syncthreads();

    const int r0 = w * 16 + g;
    // ldmatrix lane-address components (bytes)
    const uint32_t a_lane = (uint32_t)((w * 16 + ((lane >> 3) & 1) * 8 + (lane & 7)) * 144
                                       + ((lane >> 4) & 1) * 16);
    const uint32_t k_lane = (uint32_t)((((lane >> 4) & 1) * 8 + (lane & 7)) * 144
                                       + ((lane >> 3) & 1) * 16);
    const uint32_t v_lane = (uint32_t)((((lane >> 3) & 1) * 8 + (lane & 7)) * 144
                                       + ((lane >> 4) & 1) * 16);

    // Q fragments: 4 k-chunks of 16
    uint32_t qa[4][4];
#pragma unroll
    for (int kc = 0; kc < 4; kc++)
        LDSM_X4(qa[kc][0], qa[kc][1], qa[kc][2], qa[kc][3],
                sb + HPOFF + a_lane + kc * 32);
    __syncthreads();       // Q reads done before P overwrites

    float o[8][4];
#pragma unroll
    for (int i = 0; i < 8; i++)
#pragma unroll
        for (int j = 0; j < 4; j++) o[i][j] = 0.f;
    float m0 = -1e30f, m1 = -1e30f, l0 = 0.f, l1 = 0.f;

    for (int t = 0; t <= tmax; t++) {
        const int st = t & 1;
        CP_WAIT(0);        // K/V tile t arrived
        __syncthreads();
        if (t < tmax) HISSUE(t + 1);

        // --- S = Q @ K^T  (Q pre-scaled)
        float s[8][4];
#pragma unroll
        for (int i = 0; i < 8; i++)
#pragma unroll
            for (int j = 0; j < 4; j++) s[i][j] = 0.f;

#pragma unroll
        for (int kc = 0; kc < 4; kc++) {
            uint32_t kb[8][2];
#pragma unroll
            for (int ntp = 0; ntp < 4; ntp++)
                LDSM_X4(kb[2 * ntp][0], kb[2 * ntp][1],
                        kb[2 * ntp + 1][0], kb[2 * ntp + 1][1],
                        sb + HKOFF(st) + k_lane + (uint32_t)(ntp * 16 * 144) + kc * 32);
#pragma unroll
            for (int nt = 0; nt < 8; nt++)
                mma_f16(s[nt], qa[kc], kb[nt]);
        }

        // --- causal mask (last two key tiles)
        if (t >= 2 * qblk) {
            const int qg0 = q0 + r0;
            const int qg1 = qg0 + 8;
            const int kb0 = t * 64;
#pragma unroll
            for (int nt = 0; nt < 8; nt++) {
                const int col = kb0 + 8 * nt + 2 * tig;
                if (col > qg0)     s[nt][0] = -1e30f;
                if (col + 1 > qg0) s[nt][1] = -1e30f;
                if (col > qg1)     s[nt][2] = -1e30f;
                if (col + 1 > qg1) s[nt][3] = -1e30f;
            }
        }

        // --- online softmax
        float mx0 = -1e30f, mx1 = -1e30f;
#pragma unroll
        for (int nt = 0; nt < 8; nt++) {
            mx0 = fmaxf(mx0, fmaxf(s[nt][0], s[nt][1]));
            mx1 = fmaxf(mx1, fmaxf(s[nt][2], s[nt][3]));
        }
        mx0 = fmaxf(mx0, __shfl_xor_sync(0xffffffffu, mx0, 1));
        mx0 = fmaxf(mx0, __shfl_xor_sync(0xffffffffu, mx0, 2));
        mx1 = fmaxf(mx1, __shfl_xor_sync(0xffffffffu, mx1, 1));
        mx1 = fmaxf(mx1, __shfl_xor_sync(0xffffffffu, mx1, 2));

        const float mn0 = fmaxf(m0, mx0);
        const float mn1 = fmaxf(m1, mx1);
        const float a0 = __expf(m0 - mn0);
        const float a1 = __expf(m1 - mn1);
        m0 = mn0; m1 = mn1;
        l0 *= a0; l1 *= a1;
#pragma unroll
        for (int nt = 0; nt < 8; nt++) {
            o[nt][0] *= a0; o[nt][1] *= a0;
            o[nt][2] *= a1; o[nt][3] *= a1;
        }

        // --- exp, P (fp16) to smem, row sums
        __half* Ps = (__half*)(smc + HPOFF);
        float rs0 = 0.f, rs1 = 0.f;
#pragma unroll
        for (int nt = 0; nt < 8; nt++) {
            const float p0 = __expf(s[nt][0] - mn0);
            const float p1 = __expf(s[nt][1] - mn0);
            const float p2 = __expf(s[nt][2] - mn1);
            const float p3 = __expf(s[nt][3] - mn1);
            rs0 += p0 + p1;
            rs1 += p2 + p3;
            *(__half2*)(Ps + r0 * 72 + 8 * nt + 2 * tig) = __floats2half2_rn(p0, p1);
            *(__half2*)(Ps + (r0 + 8) * 72 + 8 * nt + 2 * tig) = __floats2half2_rn(p2, p3);
        }
        rs0 += __shfl_xor_sync(0xffffffffu, rs0, 1);
        rs0 += __shfl_xor_sync(0xffffffffu, rs0, 2);
        rs1 += __shfl_xor_sync(0xffffffffu, rs1, 1);
        rs1 += __shfl_xor_sync(0xffffffffu, rs1, 2);
        l0 += rs0; l1 += rs1;

        __syncwarp();      // P rows are warp-private

        // --- O += P @ V  (V fragments via ldmatrix.trans on [key][d] tile)
#pragma unroll
        for (int kc = 0; kc < 4; kc++) {
            uint32_t pa[4];
            LDSM_X4(pa[0], pa[1], pa[2], pa[3], sb + HPOFF + a_lane + kc * 32);
            uint32_t vb[8][2];
#pragma unroll
            for (int ntp = 0; ntp < 4; ntp++)
                LDSM_X4_T(vb[2 * ntp][0], vb[2 * ntp][1],
                          vb[2 * ntp + 1][0], vb[2 * ntp + 1][1],
                          sb + HVOFF(st) + v_lane + (uint32_t)(kc * 16 * 144) + ntp * 32);
#pragma unroll
            for (int nt = 0; nt < 8; nt++)
                mma_f16(o[nt], pa, vb[nt]);
        }
    }

    // --- epilogue: normalize, emit fp16 for proj GEMM
    const float inv0 = 1.0f / l0;
    const float inv1 = 1.0f / l1;
    const int b = bh >> 4, h = bh & 15;
    const size_t base0 = ((size_t)b * SS + q0 + r0) * DD + h * 64;
    const size_t base1 = ((size_t)b * SS + q0 + r0 + 8) * DD + h * 64;
#pragma unroll
    for (int nt = 0; nt < 8; nt++) {
        const int col = 8 * nt + 2 * tig;
        *(__half2*)(g_a + base0 + col) = __floats2half2_rn(o[nt][0] * inv0, o[nt][1] * inv0);
        *(__half2*)(g_a + base1 + col) = __floats2half2_rn(o[nt][2] * inv1, o[nt][3] * inv1);
    }
}

// ---------------------------------------------------------------------------
extern "C" void kernel_launch(void* const* d_in, const int* in_sizes, int n_in,
                              void* d_out, int out_size)
{
    const float* x      = (const float*)d_in[0];
    const float* w_attn = (const float*)d_in[1];
    const float* b_attn = (const float*)d_in[2];
    const float* w_proj = (const float*)d_in[3];
    const float* b_proj = (const float*)d_in[4];

    float* out  = (float*)d_out;
    float* kout = out + (size_t)BB * SS * DD;
    float* vout = kout + (size_t)BB * HH * SS * HD;

    __half *xh, *wah, *wth, *ah, *qh, *krh, *vrh;
    cudaGetSymbolAddress((void**)&xh, g_xh);
    cudaGetSymbolAddress((void**)&wah, g_wah);
    cudaGetSymbolAddress((void**)&wth, g_wth);
    cudaGetSymbolAddress((void**)&ah, g_a);
    cudaGetSymbolAddress((void**)&qh, g_qh);
    cudaGetSymbolAddress((void**)&krh, g_krh);
    cudaGetSymbolAddress((void**)&vrh, g_vrh);

    cudaFuncSetAttribute(mma_gemm_h<0>, cudaFuncAttributeMaxDynamicSharedMemorySize, GEMM_SMEM);
    cudaFuncSetAttribute(mma_gemm_h<1>, cudaFuncAttributeMaxDynamicSharedMemorySize, GEMM_SMEM);
    cudaFuncSetAttribute(attn_h, cudaFuncAttributeMaxDynamicSharedMemorySize, ATT_SMEM);

    // Convert GEMM inputs to fp16
    round_h_kernel<<<1024, 256>>>((const float4*)x, (uint2*)xh, BB * SS * DD / 4);
    round_h_kernel<<<1024, 256>>>((const float4*)w_attn, (uint2*)wah, 3 * DD * DD / 4);
    transpose_round_h_kernel<<<dim3(32, 32), dim3(32, 8)>>>(w_proj, wth);

    // QKV GEMM (fp16): q*0.125->g_qh, k/v exact->present + fp16 copies
    mma_gemm_h<1><<<dim3(3 * DD / 128, BB * SS / 128), 256, GEMM_SMEM>>>(
        xh, wah, b_attn, nullptr, kout, vout);

    // fp16 flash attention -> g_a
    attn_h<<<dim3(BB * HH, SS / 128), 256, ATT_SMEM>>>(qh, krh, vrh);

    // Proj GEMM (fp16) -> out
    mma_gemm_h<0><<<dim3(DD / 128, BB * SS / 128), 256, GEMM_SMEM>>>(
        ah, wth, b_proj, out, nullptr, nullptr);
}

// round 11
// speedup vs baseline: 1.8918x; 1.0622x over previous
#include <cuda_runtime.h>
#include <cuda_fp16.h>
#include <cstdint>

#define BB 4
#define SS 2048
#define DD 1024
#define HH 16
#define HD 64

// Scratch (allocation-free)
__device__ __half g_qh[(size_t)BB * HH * SS * HD];  // q fp16, pre-scaled by 0.125
__device__ __half g_krh[(size_t)BB * HH * SS * HD]; // k fp16 (attention input)
__device__ __half g_vrh[(size_t)BB * HH * SS * HD]; // v fp16 (attention input)
__device__ __half g_a[(size_t)BB * SS * DD];        // attention out (fp16, proj input)
__device__ __half g_xh[(size_t)BB * SS * DD];       // x in fp16
__device__ __half g_wah[(size_t)3 * DD * DD];       // w_attn in fp16
__device__ __half g_wth[(size_t)DD * DD];           // w_proj^T in fp16

// ---------------------------------------------------------------------------
__device__ __forceinline__ uint32_t smem_u32(const void* p) {
    uint32_t a;
    asm("{ .reg .u64 t; cvta.to.shared.u64 t, %1; cvt.u32.u64 %0, t; }"
        : "=r"(a) : "l"(p));
    return a;
}
__device__ __forceinline__ void cp_async16(uint32_t dst, const void* src) {
    asm volatile("cp.async.cg.shared.global [%0], [%1], 16;" :: "r"(dst), "l"(src));
}
#define CP_COMMIT() asm volatile("cp.async.commit_group;" ::: "memory")
#define CP_WAIT(n)  asm volatile("cp.async.wait_group %0;" :: "n"(n) : "memory")

__device__ __forceinline__ void mma_f16(float* c, const uint32_t* a, const uint32_t* b) {
    asm volatile(
        "mma.sync.aligned.m16n8k16.row.col.f32.f16.f16.f32 "
        "{%0,%1,%2,%3}, {%4,%5,%6,%7}, {%8,%9}, {%0,%1,%2,%3};"
        : "+f"(c[0]), "+f"(c[1]), "+f"(c[2]), "+f"(c[3])
        : "r"(a[0]), "r"(a[1]), "r"(a[2]), "r"(a[3]), "r"(b[0]), "r"(b[1]));
}
#define LDSM_X4(r0, r1, r2, r3, addr) \
    asm volatile("ldmatrix.sync.aligned.m8n8.x4.shared.b16 {%0,%1,%2,%3}, [%4];" \
        : "=r"(r0), "=r"(r1), "=r"(r2), "=r"(r3) : "r"(addr))
#define LDSM_X4_T(r0, r1, r2, r3, addr) \
    asm volatile("ldmatrix.sync.aligned.m8n8.x4.trans.shared.b16 {%0,%1,%2,%3}, [%4];" \
        : "=r"(r0), "=r"(r1), "=r"(r2), "=r"(r3) : "r"(addr))

// ---------------------------------------------------------------------------
// fp32 -> fp16 conversion
// ---------------------------------------------------------------------------
__global__ __launch_bounds__(256) void round_h_kernel(
    const float4* __restrict__ in, uint2* __restrict__ out, int n4)
{
    int i = blockIdx.x * blockDim.x + threadIdx.x;
    int stride = gridDim.x * blockDim.x;
    for (; i < n4; i += stride) {
        float4 v = in[i];
        __half2 h0 = __floats2half2_rn(v.x, v.y);
        __half2 h1 = __floats2half2_rn(v.z, v.w);
        uint2 o;
        o.x = *(uint32_t*)&h0;
        o.y = *(uint32_t*)&h1;
        out[i] = o;
    }
}

__global__ __launch_bounds__(256) void transpose_round_h_kernel(
    const float* __restrict__ in, __half* __restrict__ out)
{
    __shared__ float t[32][33];
    const int tx = threadIdx.x, ty = threadIdx.y;
    const int k0 = blockIdx.y * 32;
    const int n0 = blockIdx.x * 32;
#pragma unroll
    for (int i = ty; i < 32; i += 8)
        t[i][tx] = in[(size_t)(k0 + i) * DD + n0 + tx];
    __syncthreads();
#pragma unroll
    for (int i = ty; i < 32; i += 8)
        out[(size_t)(n0 + i) * DD + k0 + tx] = __float2half_rn(t[tx][i]);
}

// ---------------------------------------------------------------------------
// fp16 mma.sync GEMM with ldmatrix fragment loads.
// 128x128 CTA tile, 32x64 warp tile, BK=64 halfs, 3 stages, 2 CTAs/SM.
// MODE 0: C -> out0. MODE 1: q*0.125->g_qh, k->out1+g_krh, v->out2+g_vrh.
// ---------------------------------------------------------------------------
#define KDIM 1024
#define NCHUNK 16
#define HSTR 72
#define STG_H (256 * HSTR)
#define STG_BYTES (STG_H * 2)
#define GEMM_SMEM (3 * STG_BYTES)

template <int MODE>
__global__ __launch_bounds__(256, 2) void mma_gemm_h(
    const __half* __restrict__ A, const __half* __restrict__ Bm,
    const float* __restrict__ bias,
    float* __restrict__ out0, float* __restrict__ out1, float* __restrict__ out2)
{
    extern __shared__ __half smh[];
    const uint32_t sbase = smem_u32(smh);
    const int tid = threadIdx.x;
    const int wid = tid >> 5;
    const int lane = tid & 31;
    const int g = lane >> 2;
    const int tig = lane & 3;
    const int m0 = blockIdx.y * 128;
    const int n0 = blockIdx.x * 128;
    const int wm = (wid & 3) * 32;
    const int wn = (wid >> 2) * 64;

    // ldmatrix lane address components (bytes, within a 144-B/row tile)
    const uint32_t a_lane = (uint32_t)((((lane >> 3) & 1) * 8 + (lane & 7)) * 144
                                       + ((lane >> 4) & 1) * 16);
    const uint32_t b_lane = (uint32_t)((((lane >> 4) & 1) * 8 + (lane & 7)) * 144
                                       + ((lane >> 3) & 1) * 16);

    float c[2][8][4];
#pragma unroll
    for (int i = 0; i < 2; i++)
#pragma unroll
        for (int j = 0; j < 8; j++)
#pragma unroll
            for (int k = 0; k < 4; k++) c[i][j][k] = 0.f;

    const int lr = tid >> 1;
    const int lcb = (tid & 1) * 64;
    const char* Agc = (const char*)(A + (size_t)(m0 + lr) * KDIM) + lcb;
    const char* Bgc = (const char*)(Bm + (size_t)(n0 + lr) * KDIM) + lcb;

#define ISSUE(chunk) do {                                                           \
    const uint32_t _as = sbase + (uint32_t)((chunk) % 3) * STG_BYTES;               \
    const uint32_t _bs = _as + 128u * 144u;                                         \
    const int _kb = (chunk) * 128;                                                  \
    _Pragma("unroll")                                                               \
    for (int _i = 0; _i < 4; _i++)                                                  \
        cp_async16(_as + (uint32_t)(lr * 144 + lcb + _i * 16), Agc + _kb + _i * 16);\
    _Pragma("unroll")                                                               \
    for (int _i = 0; _i < 4; _i++)                                                  \
        cp_async16(_bs + (uint32_t)(lr * 144 + lcb + _i * 16), Bgc + _kb + _i * 16);\
    CP_COMMIT();                                                                    \
} while (0)

    ISSUE(0);
    ISSUE(1);

    for (int ch = 0; ch < NCHUNK; ch++) {
        if (ch + 1 < NCHUNK) { CP_WAIT(1); } else { CP_WAIT(0); }
        __syncthreads();
        if (ch + 2 < NCHUNK) ISSUE(ch + 2);

        const uint32_t aBase = sbase + (uint32_t)(ch % 3) * STG_BYTES;
        const uint32_t bBase = aBase + 128u * 144u;
#pragma unroll
        for (int ks = 0; ks < 4; ks++) {
            uint32_t af[2][4], bf[8][2];
#pragma unroll
            for (int mt = 0; mt < 2; mt++)
                LDSM_X4(af[mt][0], af[mt][1], af[mt][2], af[mt][3],
                        aBase + (uint32_t)((wm + mt * 16) * 144) + a_lane + ks * 32);
#pragma unroll
            for (int ntp = 0; ntp < 4; ntp++)
                LDSM_X4(bf[2 * ntp][0], bf[2 * ntp][1],
                        bf[2 * ntp + 1][0], bf[2 * ntp + 1][1],
                        bBase + (uint32_t)((wn + ntp * 16) * 144) + b_lane + ks * 32);
#pragma unroll
            for (int mt = 0; mt < 2; mt++)
#pragma unroll
                for (int nt = 0; nt < 8; nt++)
                    mma_f16(c[mt][nt], af[mt], bf[nt]);
        }
    }

#pragma unroll
    for (int mt = 0; mt < 2; mt++) {
        const int row0 = m0 + wm + mt * 16 + g;
        const int row1 = row0 + 8;
#pragma unroll
        for (int nt = 0; nt < 8; nt++) {
            const int n = n0 + wn + nt * 8 + 2 * tig;
            const float2 bv = *(const float2*)(bias + n);
            float2 v0, v1;
            v0.x = c[mt][nt][0] + bv.x; v0.y = c[mt][nt][1] + bv.y;
            v1.x = c[mt][nt][2] + bv.x; v1.y = c[mt][nt][3] + bv.y;
            if (MODE == 0) {
                *(float2*)(out0 + (size_t)row0 * DD + n) = v0;
                *(float2*)(out0 + (size_t)row1 * DD + n) = v1;
            } else {
                const int part = n >> 10;
                const int hc = n & (DD - 1);
                const int h = hc >> 6;
                const int d = hc & 63;
                const int b0_ = row0 >> 11, s0_ = row0 & (SS - 1);
                const int b1_ = row1 >> 11, s1_ = row1 & (SS - 1);
                const size_t d0 = (((size_t)(b0_ * HH + h)) * SS + s0_) * HD + d;
                const size_t d1 = (((size_t)(b1_ * HH + h)) * SS + s1_) * HD + d;
                if (part == 0) {
                    *(__half2*)(g_qh + d0) = __floats2half2_rn(v0.x * 0.125f, v0.y * 0.125f);
                    *(__half2*)(g_qh + d1) = __floats2half2_rn(v1.x * 0.125f, v1.y * 0.125f);
                } else if (part == 1) {
                    *(float2*)(out1 + d0) = v0;       // exact -> present
                    *(float2*)(out1 + d1) = v1;
                    *(__half2*)(g_krh + d0) = __floats2half2_rn(v0.x, v0.y);
                    *(__half2*)(g_krh + d1) = __floats2half2_rn(v1.x, v1.y);
                } else {
                    *(float2*)(out2 + d0) = v0;
                    *(float2*)(out2 + d1) = v1;
                    *(__half2*)(g_vrh + d0) = __floats2half2_rn(v0.x, v0.y);
                    *(__half2*)(g_vrh + d1) = __floats2half2_rn(v1.x, v1.y);
                }
            }
        }
    }
}

// ---------------------------------------------------------------------------
// fp16 tensor-core causal flash attention with ldmatrix (unchanged).
// ---------------------------------------------------------------------------
#define HKOFF(s) ((uint32_t)(s) * 9216u)
#define HVOFF(s) (18432u + (uint32_t)(s) * 9216u)
#define HPOFF 36864u
#define ATT_SMEM 55296

__global__ __launch_bounds__(256, 2) void attn_h(
    const __half* __restrict__ qh, const __half* __restrict__ kh,
    const __half* __restrict__ vh)
{
    extern __shared__ char smc[];
    const uint32_t sb = smem_u32(smc);
    const int tid = threadIdx.x;
    const int w = tid >> 5, lane = tid & 31;
    const int g = lane >> 2, tig = lane & 3;
    const int bh = blockIdx.x;
    const int qblk = (gridDim.y - 1) - blockIdx.y;   // heaviest blocks first
    const int q0 = qblk * 128;
    const int tmax = 2 * qblk + 1;
    const __half* kbase = kh + (size_t)bh * SS * HD;
    const __half* vbase = vh + (size_t)bh * SS * HD;

#define HISSUE(t) do {                                                             \
    const int _st = (t) & 1;                                                       \
    const int _k0 = (t) * 64;                                                      \
    _Pragma("unroll")                                                              \
    for (int _i = 0; _i < 2; _i++) {                                               \
        const int _f = tid + 256 * _i;                                             \
        const int _r = _f >> 3;                                                    \
        const int _c = (_f & 7) * 16;                                              \
        cp_async16(sb + HKOFF(_st) + (uint32_t)(_r * 144 + _c),                    \
                   (const char*)(kbase + (size_t)(_k0 + _r) * HD) + _c);           \
        cp_async16(sb + HVOFF(_st) + (uint32_t)(_r * 144 + _c),                    \
                   (const char*)(vbase + (size_t)(_k0 + _r) * HD) + _c);           \
    }                                                                              \
    CP_COMMIT();                                                                   \
} while (0)

    {
        const __half* qb = qh + ((size_t)bh * SS + q0) * HD;
#pragma unroll
        for (int i = 0; i < 4; i++) {
            const int f = tid + 256 * i;
            const int r = f >> 3;
            const int c = (f & 7) * 16;
            cp_async16(sb + HPOFF + (uint32_t)(r * 144 + c),
                       (const char*)(qb + (size_t)r * HD) + c);
        }
        CP_COMMIT();
    }
    HISSUE(0);
    CP_WAIT(1);
    __syncthreads();

    const int r0 = w * 16 + g;
    const uint32_t a_lane = (uint32_t)((w * 16 + ((lane >> 3) & 1) * 8 + (lane & 7)) * 144
                                       + ((lane >> 4) & 1) * 16);
    const uint32_t k_lane = (uint32_t)((((lane >> 4) & 1) * 8 + (lane & 7)) * 144
                                       + ((lane >> 3) & 1) * 16);
    const uint32_t v_lane = (uint32_t)((((lane >> 3) & 1) * 8 + (lane & 7)) * 144
                                       + ((lane >> 4) & 1) * 16);

    uint32_t qa[4][4];
#pragma unroll
    for (int kc = 0; kc < 4; kc++)
        LDSM_X4(qa[kc][0], qa[kc][1], qa[kc][2], qa[kc][3],
                sb + HPOFF + a_lane + kc * 32);
    __syncthreads();

    float o[8][4];
#pragma unroll
    for (int i = 0; i < 8; i++)
#pragma unroll
        for (int j = 0; j < 4; j++) o[i][j] = 0.f;
    float m0 = -1e30f, m1 = -1e30f, l0 = 0.f, l1 = 0.f;

    for (int t = 0; t <= tmax; t++) {
        const int st = t & 1;
        CP_WAIT(0);
        __syncthreads();
        if (t < tmax) HISSUE(t + 1);

        float s[8][4];
#pragma unroll
        for (int i = 0; i < 8; i++)
#pragma unroll
            for (int j = 0; j < 4; j++) s[i][j] = 0.f;

#pragma unroll
        for (int kc = 0; kc < 4; kc++) {
            uint32_t kb[8][2];
#pragma unroll
            for (int ntp = 0; ntp < 4; ntp++)
                LDSM_X4(kb[2 * ntp][0], kb[2 * ntp][1],
                        kb[2 * ntp + 1][0], kb[2 * ntp + 1][1],
                        sb + HKOFF(st) + k_lane + (uint32_t)(ntp * 16 * 144) + kc * 32);
#pragma unroll
            for (int nt = 0; nt < 8; nt++)
                mma_f16(s[nt], qa[kc], kb[nt]);
        }

        if (t >= 2 * qblk) {
            const int qg0 = q0 + r0;
            const int qg1 = qg0 + 8;
            const int kb0 = t * 64;
#pragma unroll
            for (int nt = 0; nt < 8; nt++) {
                const int col = kb0 + 8 * nt + 2 * tig;
                if (col > qg0)     s[nt][0] = -1e30f;
                if (col + 1 > qg0) s[nt][1] = -1e30f;
                if (col > qg1)     s[nt][2] = -1e30f;
                if (col + 1 > qg1) s[nt][3] = -1e30f;
            }
        }

        float mx0 = -1e30f, mx1 = -1e30f;
#pragma unroll
        for (int nt = 0; nt < 8; nt++) {
            mx0 = fmaxf(mx0, fmaxf(s[nt][0], s[nt][1]));
            mx1 = fmaxf(mx1, fmaxf(s[nt][2], s[nt][3]));
        }
        mx0 = fmaxf(mx0, __shfl_xor_sync(0xffffffffu, mx0, 1));
        mx0 = fmaxf(mx0, __shfl_xor_sync(0xffffffffu, mx0, 2));
        mx1 = fmaxf(mx1, __shfl_xor_sync(0xffffffffu, mx1, 1));
        mx1 = fmaxf(mx1, __shfl_xor_sync(0xffffffffu, mx1, 2));

        const float mn0 = fmaxf(m0, mx0);
        const float mn1 = fmaxf(m1, mx1);
        const float a0 = __expf(m0 - mn0);
        const float a1 = __expf(m1 - mn1);
        m0 = mn0; m1 = mn1;
        l0 *= a0; l1 *= a1;
#pragma unroll
        for (int nt = 0; nt < 8; nt++) {
            o[nt][0] *= a0; o[nt][1] *= a0;
            o[nt][2] *= a1; o[nt][3] *= a1;
        }

        __half* Ps = (__half*)(smc + HPOFF);
        float rs0 = 0.f, rs1 = 0.f;
#pragma unroll
        for (int nt = 0; nt < 8; nt++) {
            const float p0 = __expf(s[nt][0] - mn0);
            const float p1 = __expf(s[nt][1] - mn0);
            const float p2 = __expf(s[nt][2] - mn1);
            const float p3 = __expf(s[nt][3] - mn1);
            rs0 += p0 + p1;
            rs1 += p2 + p3;
            *(__half2*)(Ps + r0 * 72 + 8 * nt + 2 * tig) = __floats2half2_rn(p0, p1);
            *(__half2*)(Ps + (r0 + 8) * 72 + 8 * nt + 2 * tig) = __floats2half2_rn(p2, p3);
        }
        rs0 += __shfl_xor_sync(0xffffffffu, rs0, 1);
        rs0 += __shfl_xor_sync(0xffffffffu, rs0, 2);
        rs1 += __shfl_xor_sync(0xffffffffu, rs1, 1);
        rs1 += __shfl_xor_sync(0xffffffffu, rs1, 2);
        l0 += rs0; l1 += rs1;

        __syncwarp();

#pragma unroll
        for (int kc = 0; kc < 4; kc++) {
            uint32_t pa[4];
            LDSM_X4(pa[0], pa[1], pa[2], pa[3], sb + HPOFF + a_lane + kc * 32);
            uint32_t vb[8][2];
#pragma unroll
            for (int ntp = 0; ntp < 4; ntp++)
                LDSM_X4_T(vb[2 * ntp][0], vb[2 * ntp][1],
                          vb[2 * ntp + 1][0], vb[2 * ntp + 1][1],
                          sb + HVOFF(st) + v_lane + (uint32_t)(kc * 16 * 144) + ntp * 32);
#pragma unroll
            for (int nt = 0; nt < 8; nt++)
                mma_f16(o[nt], pa, vb[nt]);
        }
    }

    const float inv0 = 1.0f / l0;
    const float inv1 = 1.0f / l1;
    const int b = bh >> 4, h = bh & 15;
    const size_t base0 = ((size_t)b * SS + q0 + r0) * DD + h * 64;
    const size_t base1 = ((size_t)b * SS + q0 + r0 + 8) * DD + h * 64;
#pragma unroll
    for (int nt = 0; nt < 8; nt++) {
        const int col = 8 * nt + 2 * tig;
        *(__half2*)(g_a + base0 + col) = __floats2half2_rn(o[nt][0] * inv0, o[nt][1] * inv0);
        *(__half2*)(g_a + base1 + col) = __floats2half2_rn(o[nt][2] * inv1, o[nt][3] * inv1);
    }
}

// ---------------------------------------------------------------------------
extern "C" void kernel_launch(void* const* d_in, const int* in_sizes, int n_in,
                              void* d_out, int out_size)
{
    const float* x      = (const float*)d_in[0];
    const float* w_attn = (const float*)d_in[1];
    const float* b_attn = (const float*)d_in[2];
    const float* w_proj = (const float*)d_in[3];
    const float* b_proj = (const float*)d_in[4];

    float* out  = (float*)d_out;
    float* kout = out + (size_t)BB * SS * DD;
    float* vout = kout + (size_t)BB * HH * SS * HD;

    __half *xh, *wah, *wth, *ah, *qh, *krh, *vrh;
    cudaGetSymbolAddress((void**)&xh, g_xh);
    cudaGetSymbolAddress((void**)&wah, g_wah);
    cudaGetSymbolAddress((void**)&wth, g_wth);
    cudaGetSymbolAddress((void**)&ah, g_a);
    cudaGetSymbolAddress((void**)&qh, g_qh);
    cudaGetSymbolAddress((void**)&krh, g_krh);
    cudaGetSymbolAddress((void**)&vrh, g_vrh);

    cudaFuncSetAttribute(mma_gemm_h<0>, cudaFuncAttributeMaxDynamicSharedMemorySize, GEMM_SMEM);
    cudaFuncSetAttribute(mma_gemm_h<1>, cudaFuncAttributeMaxDynamicSharedMemorySize, GEMM_SMEM);
    cudaFuncSetAttribute(attn_h, cudaFuncAttributeMaxDynamicSharedMemorySize, ATT_SMEM);

    // Convert GEMM inputs to fp16
    round_h_kernel<<<1024, 256>>>((const float4*)x, (uint2*)xh, BB * SS * DD / 4);
    round_h_kernel<<<1024, 256>>>((const float4*)w_attn, (uint2*)wah, 3 * DD * DD / 4);
    transpose_round_h_kernel<<<dim3(32, 32), dim3(32, 8)>>>(w_proj, wth);

    // QKV GEMM (fp16): q*0.125->g_qh, k/v exact->present + fp16 copies
    mma_gemm_h<1><<<dim3(3 * DD / 128, BB * SS / 128), 256, GEMM_SMEM>>>(
        xh, wah, b_attn, nullptr, kout, vout);

    // fp16 flash attention -> g_a
    attn_h<<<dim3(BB * HH, SS / 128), 256, ATT_SMEM>>>(qh, krh, vrh);

    // Proj GEMM (fp16) -> out
    mma_gemm_h<0><<<dim3(DD / 128, BB * SS / 128), 256, GEMM_SMEM>>>(
        ah, wth, b_proj, out, nullptr, nullptr);
}